// round 2
// baseline (speedup 1.0000x reference)
#include <cuda_runtime.h>
#include <cuda_bf16.h>
#include <math.h>

// Problem constants
#define BS   2
#define SEQ  2048
#define DMODEL 1024
#define NH   16
#define HD   64
#define M_GEMM (BS*SEQ)        // 4096
#define N_GEMM (3*DMODEL)      // 3072
#define K_GEMM (DMODEL)        // 1024

#define ELEMS_PER_TENSOR (BS*NH*SEQ*HD)  // 4,194,304

typedef unsigned long long ull;

// Scratch for Q in [b,h,s,d] layout (16 MB).
__device__ float g_Qbuf[ELEMS_PER_TENSOR];

// ---------------------------------------------------------------------------
// Packed f32x2 helpers (sm_100+ PTX)
// ---------------------------------------------------------------------------
__device__ __forceinline__ ull pack2(float a, float b) {
    ull r; asm("mov.b64 %0, {%1, %2};" : "=l"(r) : "f"(a), "f"(b)); return r;
}
__device__ __forceinline__ void unpack2(ull v, float& a, float& b) {
    asm("mov.b64 {%0, %1}, %2;" : "=f"(a), "=f"(b) : "l"(v));
}
__device__ __forceinline__ void fma2(ull& d, ull a, ull b) {
    asm("fma.rn.f32x2 %0, %1, %2, %0;" : "+l"(d) : "l"(a), "l"(b));
}
__device__ __forceinline__ void mul2ip(ull& d, ull a) {
    asm("mul.rn.f32x2 %0, %1, %0;" : "+l"(d) : "l"(a));
}

// ---------------------------------------------------------------------------
// Kernel 1: QKV projection GEMM (f32x2 math) with scatter epilogue.
//   qkv[m,n] = sum_k X[m,k]*W[n,k] + bias[n]
//   128x128 tile, BK=16, 256 threads, 8x8 micro-tile (as 8x4 packed pairs).
// ---------------------------------------------------------------------------
__global__ __launch_bounds__(256)
void qkv_gemm_kernel(const float* __restrict__ X,
                     const float* __restrict__ W,
                     const float* __restrict__ bias,
                     float* __restrict__ Qbuf,
                     float* __restrict__ Kout,
                     float* __restrict__ Vout)
{
    __shared__ float As[16][128];   // [k][m]
    __shared__ float Bs[16][128];   // [k][n]

    const int bm = blockIdx.y * 128;
    const int bn = blockIdx.x * 128;
    const int tid = threadIdx.x;
    const int tx = tid & 15;          // n micro
    const int ty = tid >> 4;          // m micro

    const int lr = tid >> 2;          // row 0..63 (first half)
    const int lc = (tid & 3) * 4;     // k offset 0,4,8,12

    ull acc2[8][4];
    #pragma unroll
    for (int i = 0; i < 8; i++)
        #pragma unroll
        for (int j = 0; j < 4; j++) acc2[i][j] = 0ULL;

    for (int k0 = 0; k0 < K_GEMM; k0 += 16) {
        #pragma unroll
        for (int half = 0; half < 2; half++) {
            int row = lr + half * 64;
            float4 v = *(const float4*)(&X[(size_t)(bm + row) * K_GEMM + k0 + lc]);
            As[lc + 0][row] = v.x; As[lc + 1][row] = v.y;
            As[lc + 2][row] = v.z; As[lc + 3][row] = v.w;
            float4 w = *(const float4*)(&W[(size_t)(bn + row) * K_GEMM + k0 + lc]);
            Bs[lc + 0][row] = w.x; Bs[lc + 1][row] = w.y;
            Bs[lc + 2][row] = w.z; Bs[lc + 3][row] = w.w;
        }
        __syncthreads();

        #pragma unroll
        for (int kk = 0; kk < 16; kk++) {
            float4 av0 = *(const float4*)(&As[kk][ty * 8]);
            float4 av1 = *(const float4*)(&As[kk][ty * 8 + 4]);
            ulonglong2 bv0 = *(const ulonglong2*)(&Bs[kk][tx * 8]);
            ulonglong2 bv1 = *(const ulonglong2*)(&Bs[kk][tx * 8 + 4]);
            ull b2[4] = { bv0.x, bv0.y, bv1.x, bv1.y };
            ull a2[8];
            a2[0] = pack2(av0.x, av0.x); a2[1] = pack2(av0.y, av0.y);
            a2[2] = pack2(av0.z, av0.z); a2[3] = pack2(av0.w, av0.w);
            a2[4] = pack2(av1.x, av1.x); a2[5] = pack2(av1.y, av1.y);
            a2[6] = pack2(av1.z, av1.z); a2[7] = pack2(av1.w, av1.w);
            #pragma unroll
            for (int i = 0; i < 8; i++)
                #pragma unroll
                for (int j = 0; j < 4; j++)
                    fma2(acc2[i][j], a2[i], b2[j]);
        }
        __syncthreads();
    }

    // Epilogue: unpack + bias, scatter to [b,h,s,d]
    #pragma unroll
    for (int i = 0; i < 8; i++) {
        const int m = bm + ty * 8 + i;
        const int b = m >> 11;
        const int s = m & (SEQ - 1);
        float accr[8];
        #pragma unroll
        for (int j = 0; j < 4; j++) unpack2(acc2[i][j], accr[2*j], accr[2*j+1]);
        #pragma unroll
        for (int j = 0; j < 8; j++) {
            const int n = bn + tx * 8 + j;
            const int t = n >> 10;
            const int h = (n >> 6) & (NH - 1);
            const int d = n & (HD - 1);
            const size_t idx = (((size_t)(b * NH + h)) * SEQ + s) * HD + d;
            const float v = accr[j] + bias[n];
            if (t == 0)      Qbuf[idx] = v;
            else if (t == 1) Kout[idx] = v;
            else             Vout[idx] = v;
        }
    }
}

// ---------------------------------------------------------------------------
// Kernel 2: causal flash attention, fp32 with packed f32x2 math.
//   One thread owns one query row (q + acc packed in 64-bit regs).
//   128 threads -> 128 query rows. Key tiles of 64 in smem.
// ---------------------------------------------------------------------------
__global__ __launch_bounds__(128)
void attn_kernel(const float* __restrict__ Qbuf,
                 const float* __restrict__ Kbuf,
                 const float* __restrict__ Vbuf,
                 float* __restrict__ Out)
{
    __shared__ float Ks[64][64];
    __shared__ float Vs[64][64];

    const int bh = blockIdx.y;           // 0..31
    const int b  = bh >> 4;
    const int h  = bh & (NH - 1);
    const int qt = blockIdx.x;           // 0..15
    const int tid = threadIdx.x;         // 0..127
    const int qidx = qt * 128 + tid;

    // Load q, pre-scale by 1/sqrt(HD), pack into 32 f32x2 regs
    const float* qptr = Qbuf + ((size_t)bh * SEQ + qidx) * HD;
    ull q2[HD / 2];
    #pragma unroll
    for (int i = 0; i < HD / 4; i++) {
        float4 v = *(const float4*)(qptr + i * 4);
        q2[2*i + 0] = pack2(v.x * 0.125f, v.y * 0.125f);
        q2[2*i + 1] = pack2(v.z * 0.125f, v.w * 0.125f);
    }

    ull acc2[HD / 2];
    #pragma unroll
    for (int d = 0; d < HD / 2; d++) acc2[d] = 0ULL;
    float mrow = -INFINITY, lsum = 0.f;

    const float* Kb = Kbuf + (size_t)bh * SEQ * HD;
    const float* Vb = Vbuf + (size_t)bh * SEQ * HD;

    const int ktmax = 2 * qt + 1;

    for (int kt = 0; kt <= ktmax; kt++) {
        const size_t base = (size_t)kt * 64 * HD;
        #pragma unroll
        for (int r = 0; r < 8; r++) {
            const int fidx = tid + r * 128;
            const int row = fidx >> 4;
            const int c   = (fidx & 15) * 4;
            *(float4*)(&Ks[row][c]) = *(const float4*)(Kb + base + row * HD + c);
            *(float4*)(&Vs[row][c]) = *(const float4*)(Vb + base + row * HD + c);
        }
        __syncthreads();

        int jmax = qidx - kt * 64 + 1;
        if (jmax > 64) jmax = 64;
        for (int j = 0; j < jmax; j++) {
            // QK dot: 16 LDS.128 + 32 FMA2, 4 independent chains
            const ulonglong2* kr = (const ulonglong2*)(&Ks[j][0]);
            ull s2a = 0ULL, s2b = 0ULL, s2c = 0ULL, s2d = 0ULL;
            #pragma unroll
            for (int t = 0; t < 8; t++) {
                ulonglong2 k0 = kr[2*t];
                ulonglong2 k1 = kr[2*t + 1];
                fma2(s2a, q2[4*t + 0], k0.x);
                fma2(s2b, q2[4*t + 1], k0.y);
                fma2(s2c, q2[4*t + 2], k1.x);
                fma2(s2d, q2[4*t + 3], k1.y);
            }
            float ax, ay, bx, by, cx, cy, dx, dy;
            unpack2(s2a, ax, ay); unpack2(s2b, bx, by);
            unpack2(s2c, cx, cy); unpack2(s2d, dx, dy);
            const float s = ((ax + ay) + (bx + by)) + ((cx + cy) + (dx + dy));

            if (s > mrow) {
                const float alpha = __expf(mrow - s);   // exp(-inf)=0 on init
                lsum *= alpha;
                const ull al2 = pack2(alpha, alpha);
                #pragma unroll
                for (int d = 0; d < HD / 2; d++) mul2ip(acc2[d], al2);
                mrow = s;
            }
            const float p = __expf(s - mrow);
            lsum += p;
            const ull p2 = pack2(p, p);

            const ulonglong2* vr = (const ulonglong2*)(&Vs[j][0]);
            #pragma unroll
            for (int t = 0; t < 16; t++) {
                ulonglong2 v = vr[t];
                fma2(acc2[2*t + 0], p2, v.x);
                fma2(acc2[2*t + 1], p2, v.y);
            }
        }
        __syncthreads();
    }

    const float inv = 1.0f / lsum;
    float* op = Out + ((size_t)b * SEQ + qidx) * DMODEL + h * HD;
    #pragma unroll
    for (int d = 0; d < HD / 4; d++) {
        float x0, x1, x2, x3;
        unpack2(acc2[2*d + 0], x0, x1);
        unpack2(acc2[2*d + 1], x2, x3);
        float4 v;
        v.x = x0 * inv; v.y = x1 * inv; v.z = x2 * inv; v.w = x3 * inv;
        *(float4*)(op + 4 * d) = v;
    }
}

// ---------------------------------------------------------------------------
extern "C" void kernel_launch(void* const* d_in, const int* in_sizes, int n_in,
                              void* d_out, int out_size)
{
    const float* X    = (const float*)d_in[0];
    const float* Wqkv = (const float*)d_in[1];
    const float* bqkv = (const float*)d_in[2];

    float* out  = (float*)d_out;
    float* Kout = (float*)d_out + ELEMS_PER_TENSOR;
    float* Vout = (float*)d_out + 2 * (size_t)ELEMS_PER_TENSOR;

    float* Qbuf;
    cudaGetSymbolAddress((void**)&Qbuf, g_Qbuf);

    dim3 ggrid(N_GEMM / 128, M_GEMM / 128);
    qkv_gemm_kernel<<<ggrid, 256>>>(X, Wqkv, bqkv, Qbuf, Kout, Vout);

    dim3 agrid(SEQ / 128, BS * NH);
    attn_kernel<<<agrid, 128>>>(Qbuf, Kout, Vout, out);
}

// round 4
// speedup vs baseline: 2.4184x; 2.4184x over previous
#include <cuda_runtime.h>
#include <cuda_bf16.h>
#include <math.h>

#define BS   2
#define SEQ  2048
#define DMODEL 1024
#define NH   16
#define HD   64
#define M_GEMM 4096
#define N_GEMM 3072
#define K_GEMM 1024
#define ELEMS_PER_TENSOR (BS*SEQ*DMODEL)

__device__ float g_Qbuf[ELEMS_PER_TENSOR];

// ---------------------------------------------------------------------------
// helpers
// ---------------------------------------------------------------------------
__device__ __forceinline__ unsigned pack_bf16(float a, float b) {
    __nv_bfloat162 t;
    t.x = __float2bfloat16_rn(a);
    t.y = __float2bfloat16_rn(b);
    return *reinterpret_cast<unsigned*>(&t);
}

// split (a,b) into bf16 hi plane (packed) and bf16 lo plane (packed)
__device__ __forceinline__ void split_pack(float a, float b, unsigned& h, unsigned& l) {
    __nv_bfloat16 ah = __float2bfloat16_rn(a);
    __nv_bfloat16 bh = __float2bfloat16_rn(b);
    float alo = a - __bfloat162float(ah);
    float blo = b - __bfloat162float(bh);
    __nv_bfloat162 hv; hv.x = ah; hv.y = bh;
    h = *reinterpret_cast<unsigned*>(&hv);
    l = pack_bf16(alo, blo);
}

__device__ __forceinline__ void mma16816(float* d, const unsigned* a, unsigned b0, unsigned b1) {
    asm volatile(
        "mma.sync.aligned.m16n8k16.row.col.f32.bf16.bf16.f32 "
        "{%0,%1,%2,%3}, {%4,%5,%6,%7}, {%8,%9}, {%0,%1,%2,%3};"
        : "+f"(d[0]), "+f"(d[1]), "+f"(d[2]), "+f"(d[3])
        : "r"(a[0]), "r"(a[1]), "r"(a[2]), "r"(a[3]), "r"(b0), "r"(b1));
}

// ---------------------------------------------------------------------------
// Kernel 1: QKV GEMM, bf16x3 emulated fp32 on tensor cores.
// Block tile 128x128, BK=32, 256 threads = 8 warps (2m x 4n), warp tile 64x32.
// ---------------------------------------------------------------------------
#define GST 40   // smem k-stride (32 + 8 pad)

__global__ __launch_bounds__(256)
void qkv_gemm_tc(const float* __restrict__ X, const float* __restrict__ W,
                 const float* __restrict__ bias,
                 float* __restrict__ Qbuf, float* __restrict__ Kout, float* __restrict__ Vout)
{
    __shared__ __nv_bfloat16 Ah[128][GST], Al[128][GST];
    __shared__ __nv_bfloat16 Bh[128][GST], Bl[128][GST];

    const int tid = threadIdx.x;
    const int w = tid >> 5, lane = tid & 31;
    const int wm = w & 1, wn = w >> 1;           // warp m-origin wm*64, n-origin wn*32
    const int gr = lane >> 2, qc = lane & 3;
    const int bm = blockIdx.y * 128, bn = blockIdx.x * 128;

    const int lrow = tid >> 1;                   // 0..127
    const int lcol = (tid & 1) * 16;             // 0 / 16 (covers 32 cols with 2 thr/row)

    float acc[4][4][4];
    #pragma unroll
    for (int i = 0; i < 4; i++)
        #pragma unroll
        for (int j = 0; j < 4; j++)
            #pragma unroll
            for (int e = 0; e < 4; e++) acc[i][j][e] = 0.f;

    for (int k0 = 0; k0 < K_GEMM; k0 += 32) {
        #pragma unroll
        for (int u = 0; u < 4; u++) {
            float4 v = *(const float4*)&X[(size_t)(bm + lrow) * K_GEMM + k0 + lcol + u * 4];
            unsigned h0, l0, h1, l1;
            split_pack(v.x, v.y, h0, l0); split_pack(v.z, v.w, h1, l1);
            *(unsigned*)&Ah[lrow][lcol + u*4]     = h0;
            *(unsigned*)&Ah[lrow][lcol + u*4 + 2] = h1;
            *(unsigned*)&Al[lrow][lcol + u*4]     = l0;
            *(unsigned*)&Al[lrow][lcol + u*4 + 2] = l1;
            float4 wv = *(const float4*)&W[(size_t)(bn + lrow) * K_GEMM + k0 + lcol + u * 4];
            split_pack(wv.x, wv.y, h0, l0); split_pack(wv.z, wv.w, h1, l1);
            *(unsigned*)&Bh[lrow][lcol + u*4]     = h0;
            *(unsigned*)&Bh[lrow][lcol + u*4 + 2] = h1;
            *(unsigned*)&Bl[lrow][lcol + u*4]     = l0;
            *(unsigned*)&Bl[lrow][lcol + u*4 + 2] = l1;
        }
        __syncthreads();

        #pragma unroll
        for (int kt = 0; kt < 2; kt++) {
            const int kb = kt * 16;
            unsigned ah[4][4], al[4][4];
            #pragma unroll
            for (int i = 0; i < 4; i++) {
                int r = wm * 64 + i * 16 + gr;
                ah[i][0] = *(unsigned*)&Ah[r    ][kb + qc*2];
                ah[i][1] = *(unsigned*)&Ah[r + 8][kb + qc*2];
                ah[i][2] = *(unsigned*)&Ah[r    ][kb + qc*2 + 8];
                ah[i][3] = *(unsigned*)&Ah[r + 8][kb + qc*2 + 8];
                al[i][0] = *(unsigned*)&Al[r    ][kb + qc*2];
                al[i][1] = *(unsigned*)&Al[r + 8][kb + qc*2];
                al[i][2] = *(unsigned*)&Al[r    ][kb + qc*2 + 8];
                al[i][3] = *(unsigned*)&Al[r + 8][kb + qc*2 + 8];
            }
            #pragma unroll
            for (int j = 0; j < 4; j++) {
                int n = wn * 32 + j * 8 + gr;
                unsigned bh0 = *(unsigned*)&Bh[n][kb + qc*2];
                unsigned bh1 = *(unsigned*)&Bh[n][kb + qc*2 + 8];
                unsigned bl0 = *(unsigned*)&Bl[n][kb + qc*2];
                unsigned bl1 = *(unsigned*)&Bl[n][kb + qc*2 + 8];
                #pragma unroll
                for (int i = 0; i < 4; i++) {
                    mma16816(acc[i][j], ah[i], bh0, bh1);   // hi*hi
                    mma16816(acc[i][j], ah[i], bl0, bl1);   // hi*lo
                    mma16816(acc[i][j], al[i], bh0, bh1);   // lo*hi
                }
            }
        }
        __syncthreads();
    }

    // Epilogue: bias + scatter to [b,h,s,d] (Q scratch / K,V outputs)
    #pragma unroll
    for (int i = 0; i < 4; i++) {
        #pragma unroll
        for (int e = 0; e < 4; e++) {
            const int m = bm + wm * 64 + i * 16 + gr + (e >> 1) * 8;
            const int b = m >> 11;
            const int s = m & (SEQ - 1);
            #pragma unroll
            for (int j = 0; j < 4; j++) {
                const int n = bn + wn * 32 + j * 8 + qc * 2 + (e & 1);
                const int t = n >> 10;
                const int h = (n >> 6) & (NH - 1);
                const int d = n & (HD - 1);
                const size_t idx = (((size_t)(b * NH + h)) * SEQ + s) * HD + d;
                const float v = acc[i][j][e] + bias[n];
                if (t == 0)      Qbuf[idx] = v;
                else if (t == 1) Kout[idx] = v;
                else             Vout[idx] = v;
            }
        }
    }
}

// ---------------------------------------------------------------------------
// Kernel 2: causal flash attention (FA2), bf16x3 on tensor cores.
// Block: 128 threads = 4 warps; Q tile 64 rows (16/warp); K/V tiles 64.
// grid = (SEQ/64, BS*NH)
// ---------------------------------------------------------------------------
#define KST 72   // 64 + 8 pad

__global__ __launch_bounds__(128)
void attn_tc(const float* __restrict__ Qbuf, const float* __restrict__ Kbuf,
             const float* __restrict__ Vbuf, float* __restrict__ Out)
{
    __shared__ __nv_bfloat16 Kh[64][KST], Kl[64][KST];     // [key][d]
    __shared__ __nv_bfloat16 Vth[64][KST], Vtl[64][KST];   // [d][key] (transposed)

    const int bh = blockIdx.y;
    const int b = bh >> 4, h = bh & (NH - 1);
    const int qt = blockIdx.x;
    const int tid = threadIdx.x, w = tid >> 5, lane = tid & 31;
    const int gr = lane >> 2, qc = lane & 3;
    const int m0 = qt * 64 + w * 16;             // warp q-row origin (global)

    // Q fragments, register resident, scaled by 1/sqrt(HD) then hi/lo split
    unsigned qh[4][4], ql[4][4];
    {
        const float* Qp = Qbuf + (size_t)bh * SEQ * HD;
        #pragma unroll
        for (int kc = 0; kc < 4; kc++) {
            #pragma unroll
            for (int e = 0; e < 4; e++) {
                int r = m0 + gr + (e & 1) * 8;
                int c = kc * 16 + qc * 2 + (e >> 1) * 8;
                float2 v = *(const float2*)&Qp[(size_t)r * HD + c];
                split_pack(v.x * 0.125f, v.y * 0.125f, qh[kc][e], ql[kc][e]);
            }
        }
    }

    float Oa[8][4];
    #pragma unroll
    for (int jd = 0; jd < 8; jd++)
        #pragma unroll
        for (int e = 0; e < 4; e++) Oa[jd][e] = 0.f;
    float mrow0 = -INFINITY, mrow1 = -INFINITY, lsum0 = 0.f, lsum1 = 0.f;

    const float* Kb = Kbuf + (size_t)bh * SEQ * HD;
    const float* Vb = Vbuf + (size_t)bh * SEQ * HD;

    // FIXED loader mapping: 128 threads cover full 64x64 tile.
    // 2 threads per row, each thread covers 32 columns (8 x float4).
    const int lrow = tid >> 1;                 // 0..63
    const int lcol = (tid & 1) * 32;           // 0 / 32

    for (int kt = 0; kt <= qt; kt++) {
        // ---- cooperative load + split K (row layout) and V (transposed) ----
        const float* Ksrc = Kb + (size_t)kt * 64 * HD;
        const float* Vsrc = Vb + (size_t)kt * 64 * HD;
        #pragma unroll
        for (int u = 0; u < 8; u++) {
            float4 v = *(const float4*)&Ksrc[(size_t)lrow * HD + lcol + u * 4];
            unsigned h0, l0, h1, l1;
            split_pack(v.x, v.y, h0, l0); split_pack(v.z, v.w, h1, l1);
            *(unsigned*)&Kh[lrow][lcol + u*4]     = h0;
            *(unsigned*)&Kh[lrow][lcol + u*4 + 2] = h1;
            *(unsigned*)&Kl[lrow][lcol + u*4]     = l0;
            *(unsigned*)&Kl[lrow][lcol + u*4 + 2] = l1;

            float4 vv = *(const float4*)&Vsrc[(size_t)lrow * HD + lcol + u * 4];
            #pragma unroll
            for (int x = 0; x < 4; x++) {
                float f = ((const float*)&vv)[x];
                __nv_bfloat16 fh = __float2bfloat16_rn(f);
                Vth[lcol + u*4 + x][lrow] = fh;
                Vtl[lcol + u*4 + x][lrow] = __float2bfloat16_rn(f - __bfloat162float(fh));
            }
        }
        __syncthreads();

        // ---- S = Q K^T (bf16x3) ----
        float S[8][4];
        #pragma unroll
        for (int j = 0; j < 8; j++)
            #pragma unroll
            for (int e = 0; e < 4; e++) S[j][e] = 0.f;

        #pragma unroll
        for (int kk = 0; kk < 4; kk++) {
            const int c0 = kk * 16 + qc * 2;
            #pragma unroll
            for (int j = 0; j < 8; j++) {
                int n = j * 8 + gr;
                unsigned bh0 = *(unsigned*)&Kh[n][c0];
                unsigned bh1 = *(unsigned*)&Kh[n][c0 + 8];
                unsigned bl0 = *(unsigned*)&Kl[n][c0];
                unsigned bl1 = *(unsigned*)&Kl[n][c0 + 8];
                mma16816(S[j], qh[kk], bh0, bh1);
                mma16816(S[j], qh[kk], bl0, bl1);
                mma16816(S[j], ql[kk], bh0, bh1);
            }
        }

        // ---- causal mask on diagonal tile ----
        if (kt == qt) {
            const int r0 = w * 16 + gr, r1 = r0 + 8;
            #pragma unroll
            for (int j = 0; j < 8; j++) {
                const int cn = j * 8 + qc * 2;
                if (cn     > r0) S[j][0] = -1e30f;
                if (cn + 1 > r0) S[j][1] = -1e30f;
                if (cn     > r1) S[j][2] = -1e30f;
                if (cn + 1 > r1) S[j][3] = -1e30f;
            }
        }

        // ---- online softmax ----
        float mx0 = -1e30f, mx1 = -1e30f;
        #pragma unroll
        for (int j = 0; j < 8; j++) {
            mx0 = fmaxf(mx0, fmaxf(S[j][0], S[j][1]));
            mx1 = fmaxf(mx1, fmaxf(S[j][2], S[j][3]));
        }
        mx0 = fmaxf(mx0, __shfl_xor_sync(0xffffffff, mx0, 1));
        mx0 = fmaxf(mx0, __shfl_xor_sync(0xffffffff, mx0, 2));
        mx1 = fmaxf(mx1, __shfl_xor_sync(0xffffffff, mx1, 1));
        mx1 = fmaxf(mx1, __shfl_xor_sync(0xffffffff, mx1, 2));

        const float mnew0 = fmaxf(mrow0, mx0), mnew1 = fmaxf(mrow1, mx1);
        const float alpha0 = __expf(mrow0 - mnew0), alpha1 = __expf(mrow1 - mnew1);
        mrow0 = mnew0; mrow1 = mnew1;
        lsum0 *= alpha0; lsum1 *= alpha1;
        #pragma unroll
        for (int jd = 0; jd < 8; jd++) {
            Oa[jd][0] *= alpha0; Oa[jd][1] *= alpha0;
            Oa[jd][2] *= alpha1; Oa[jd][3] *= alpha1;
        }

        float rs0 = 0.f, rs1 = 0.f;
        #pragma unroll
        for (int j = 0; j < 8; j++) {
            S[j][0] = __expf(S[j][0] - mnew0);
            S[j][1] = __expf(S[j][1] - mnew0);
            S[j][2] = __expf(S[j][2] - mnew1);
            S[j][3] = __expf(S[j][3] - mnew1);
            rs0 += S[j][0] + S[j][1];
            rs1 += S[j][2] + S[j][3];
        }
        rs0 += __shfl_xor_sync(0xffffffff, rs0, 1);
        rs0 += __shfl_xor_sync(0xffffffff, rs0, 2);
        rs1 += __shfl_xor_sync(0xffffffff, rs1, 1);
        rs1 += __shfl_xor_sync(0xffffffff, rs1, 2);
        lsum0 += rs0; lsum1 += rs1;

        // ---- O += P V  (bf16x3; P frags from S registers) ----
        #pragma unroll
        for (int kk = 0; kk < 4; kk++) {
            unsigned ph[4], pl[4];
            const int j0 = kk * 2, j1 = kk * 2 + 1;
            split_pack(S[j0][0], S[j0][1], ph[0], pl[0]);
            split_pack(S[j0][2], S[j0][3], ph[1], pl[1]);
            split_pack(S[j1][0], S[j1][1], ph[2], pl[2]);
            split_pack(S[j1][2], S[j1][3], ph[3], pl[3]);
            const int c0 = kk * 16 + qc * 2;
            #pragma unroll
            for (int jd = 0; jd < 8; jd++) {
                int d = jd * 8 + gr;
                unsigned vh0 = *(unsigned*)&Vth[d][c0];
                unsigned vh1 = *(unsigned*)&Vth[d][c0 + 8];
                unsigned vl0 = *(unsigned*)&Vtl[d][c0];
                unsigned vl1 = *(unsigned*)&Vtl[d][c0 + 8];
                mma16816(Oa[jd], ph, vh0, vh1);
                mma16816(Oa[jd], ph, vl0, vl1);
                mma16816(Oa[jd], pl, vh0, vh1);
            }
        }
        __syncthreads();
    }

    // ---- normalize + write out [b, s, h*64+d] ----
    const float inv0 = 1.f / lsum0, inv1 = 1.f / lsum1;
    float* Op = Out + ((size_t)b * SEQ + m0) * DMODEL + h * HD;
    #pragma unroll
    for (int jd = 0; jd < 8; jd++) {
        const int c = jd * 8 + qc * 2;
        float2 v0; v0.x = Oa[jd][0] * inv0; v0.y = Oa[jd][1] * inv0;
        float2 v1; v1.x = Oa[jd][2] * inv1; v1.y = Oa[jd][3] * inv1;
        *(float2*)&Op[(size_t)gr * DMODEL + c]       = v0;
        *(float2*)&Op[(size_t)(gr + 8) * DMODEL + c] = v1;
    }
}

// ---------------------------------------------------------------------------
extern "C" void kernel_launch(void* const* d_in, const int* in_sizes, int n_in,
                              void* d_out, int out_size)
{
    const float* X    = (const float*)d_in[0];
    const float* Wqkv = (const float*)d_in[1];
    const float* bqkv = (const float*)d_in[2];

    float* out  = (float*)d_out;
    float* Kout = (float*)d_out + ELEMS_PER_TENSOR;
    float* Vout = (float*)d_out + 2 * (size_t)ELEMS_PER_TENSOR;

    float* Qbuf;
    cudaGetSymbolAddress((void**)&Qbuf, g_Qbuf);

    dim3 ggrid(N_GEMM / 128, M_GEMM / 128);   // (24, 32)
    qkv_gemm_tc<<<ggrid, 256>>>(X, Wqkv, bqkv, Qbuf, Kout, Vout);

    dim3 agrid(SEQ / 64, BS * NH);            // (32, 32)
    attn_tc<<<agrid, 128>>>(Qbuf, Kout, Vout, out);
}

// round 5
// speedup vs baseline: 3.0991x; 1.2815x over previous
#include <cuda_runtime.h>
#include <cuda_bf16.h>
#include <math.h>

#define BS   2
#define SEQ  2048
#define DMODEL 1024
#define NH   16
#define HD   64
#define M_GEMM 4096
#define N_GEMM 3072
#define K_GEMM 1024
#define ELEMS (BS*SEQ*DMODEL)

// bf16 hi/lo planes (packed pairs as unsigned). Device globals => no allocation.
__device__ unsigned g_Xh[M_GEMM*K_GEMM/2], g_Xl[M_GEMM*K_GEMM/2];
__device__ unsigned g_Wh[N_GEMM*K_GEMM/2], g_Wl[N_GEMM*K_GEMM/2];
__device__ unsigned g_Qh[ELEMS/2], g_Ql[ELEMS/2];
__device__ unsigned g_Kh[ELEMS/2], g_Kl[ELEMS/2];
__device__ unsigned g_Vh[ELEMS/2], g_Vl[ELEMS/2];

// ---------------------------------------------------------------------------
// helpers
// ---------------------------------------------------------------------------
__device__ __forceinline__ unsigned pack_bf16(float a, float b) {
    __nv_bfloat162 t; t.x = __float2bfloat16_rn(a); t.y = __float2bfloat16_rn(b);
    return *reinterpret_cast<unsigned*>(&t);
}
__device__ __forceinline__ void split_pack(float a, float b, unsigned& h, unsigned& l) {
    __nv_bfloat16 ah = __float2bfloat16_rn(a);
    __nv_bfloat16 bh = __float2bfloat16_rn(b);
    __nv_bfloat162 hv; hv.x = ah; hv.y = bh;
    h = *reinterpret_cast<unsigned*>(&hv);
    l = pack_bf16(a - __bfloat162float(ah), b - __bfloat162float(bh));
}
__device__ __forceinline__ void mma16816(float* d, const unsigned* a, unsigned b0, unsigned b1) {
    asm volatile(
        "mma.sync.aligned.m16n8k16.row.col.f32.bf16.bf16.f32 "
        "{%0,%1,%2,%3}, {%4,%5,%6,%7}, {%8,%9}, {%0,%1,%2,%3};"
        : "+f"(d[0]), "+f"(d[1]), "+f"(d[2]), "+f"(d[3])
        : "r"(a[0]), "r"(a[1]), "r"(a[2]), "r"(a[3]), "r"(b0), "r"(b1));
}
__device__ __forceinline__ unsigned smem_u32(const void* p) {
    return (unsigned)__cvta_generic_to_shared(p);
}
__device__ __forceinline__ void ldsm_x4(unsigned& r0, unsigned& r1, unsigned& r2, unsigned& r3, unsigned addr) {
    asm volatile("ldmatrix.sync.aligned.m8n8.x4.shared.b16 {%0,%1,%2,%3}, [%4];"
                 : "=r"(r0), "=r"(r1), "=r"(r2), "=r"(r3) : "r"(addr));
}
__device__ __forceinline__ void ldsm_x4_t(unsigned& r0, unsigned& r1, unsigned& r2, unsigned& r3, unsigned addr) {
    asm volatile("ldmatrix.sync.aligned.m8n8.x4.trans.shared.b16 {%0,%1,%2,%3}, [%4];"
                 : "=r"(r0), "=r"(r1), "=r"(r2), "=r"(r3) : "r"(addr));
}
__device__ __forceinline__ void cp16(unsigned dst, const void* src) {
    asm volatile("cp.async.cg.shared.global [%0], [%1], 16;" :: "r"(dst), "l"(src));
}
__device__ __forceinline__ void cp_commit_wait0() {
    asm volatile("cp.async.commit_group;\ncp.async.wait_group 0;" ::: "memory");
}

// ---------------------------------------------------------------------------
// Kernel 0: split X, W into bf16 hi/lo planes
// ---------------------------------------------------------------------------
__global__ void convert_planes(const float4* __restrict__ X4, const float4* __restrict__ W4)
{
    const int i0 = blockIdx.x * blockDim.x + threadIdx.x;
    const int stride = gridDim.x * blockDim.x;
    for (int idx = i0; idx < M_GEMM * K_GEMM / 4; idx += stride) {
        float4 v = X4[idx];
        unsigned h0, l0, h1, l1;
        split_pack(v.x, v.y, h0, l0); split_pack(v.z, v.w, h1, l1);
        g_Xh[2*idx] = h0; g_Xh[2*idx+1] = h1;
        g_Xl[2*idx] = l0; g_Xl[2*idx+1] = l1;
    }
    for (int idx = i0; idx < N_GEMM * K_GEMM / 4; idx += stride) {
        float4 v = W4[idx];
        unsigned h0, l0, h1, l1;
        split_pack(v.x, v.y, h0, l0); split_pack(v.z, v.w, h1, l1);
        g_Wh[2*idx] = h0; g_Wh[2*idx+1] = h1;
        g_Wl[2*idx] = l0; g_Wl[2*idx+1] = l1;
    }
}

// ---------------------------------------------------------------------------
// Kernel 1: QKV GEMM from bf16 planes. 128x128 tile, BK=32, 8 warps (2m x 4n).
// cp.async tile loads, ldmatrix fragment loads, bf16x3 MMA.
// Epilogue: K/V fp32 outputs + Q/K/V bf16 planes.
// ---------------------------------------------------------------------------
#define GST 40   // smem row stride in bf16 elems (80B: LDSM conflict-free)

__global__ __launch_bounds__(256, 2)
void qkv_gemm_tc(const float* __restrict__ bias,
                 float* __restrict__ Kout, float* __restrict__ Vout)
{
    __shared__ __align__(16) __nv_bfloat16 Ah[128][GST], Al[128][GST];
    __shared__ __align__(16) __nv_bfloat16 Bh[128][GST], Bl[128][GST];

    const int tid = threadIdx.x;
    const int w = tid >> 5, lane = tid & 31;
    const int wm = w & 1, wn = w >> 1;
    const int gr = lane >> 2, qc = lane & 3;
    const int bm = blockIdx.y * 128, bn = blockIdx.x * 128;

    const unsigned sAh = smem_u32(&Ah[0][0]), sAl = smem_u32(&Al[0][0]);
    const unsigned sBh = smem_u32(&Bh[0][0]), sBl = smem_u32(&Bl[0][0]);

    const int lrow = tid >> 1;               // 0..127
    const int ch0  = (tid & 1) * 2;          // chunk 0/2

    float acc[4][4][4];
    #pragma unroll
    for (int i = 0; i < 4; i++)
        #pragma unroll
        for (int j = 0; j < 4; j++)
            #pragma unroll
            for (int e = 0; e < 4; e++) acc[i][j][e] = 0.f;

    for (int k0 = 0; k0 < K_GEMM; k0 += 32) {
        // ---- cp.async tile loads: 8 x 16B per thread ----
        const size_t arow = (size_t)(bm + lrow) * (K_GEMM/2) + k0/2;
        const size_t brow = (size_t)(bn + lrow) * (K_GEMM/2) + k0/2;
        #pragma unroll
        for (int c = 0; c < 2; c++) {
            const int ch = ch0 + c;
            const unsigned doff = lrow * (GST*2) + ch * 16;
            cp16(sAh + doff, &g_Xh[arow + ch*4]);
            cp16(sAl + doff, &g_Xl[arow + ch*4]);
            cp16(sBh + doff, &g_Wh[brow + ch*4]);
            cp16(sBl + doff, &g_Wl[brow + ch*4]);
        }
        cp_commit_wait0();
        __syncthreads();

        #pragma unroll
        for (int kt = 0; kt < 2; kt++) {
            // A frags via ldmatrix.x4 (non-trans)
            unsigned ah[4][4], al[4][4];
            const unsigned acol = (kt*16 + (lane >> 4) * 8) * 2;
            #pragma unroll
            for (int i = 0; i < 4; i++) {
                const unsigned aoff = (unsigned)(wm*64 + i*16 + (lane & 15)) * (GST*2) + acol;
                ldsm_x4(ah[i][0], ah[i][1], ah[i][2], ah[i][3], sAh + aoff);
                ldsm_x4(al[i][0], al[i][1], al[i][2], al[i][3], sAl + aoff);
            }
            // B frags + MMA
            const unsigned bcol = (kt*16 + ((lane >> 3) & 1) * 8) * 2;
            const unsigned brow_f = ((lane >> 4) << 3) + (lane & 7);
            #pragma unroll
            for (int jp = 0; jp < 2; jp++) {
                const unsigned boff = (unsigned)(wn*32 + jp*16 + brow_f) * (GST*2) + bcol;
                unsigned h0,h1,h2,h3, l0,l1,l2,l3;
                ldsm_x4(h0, h1, h2, h3, sBh + boff);
                ldsm_x4(l0, l1, l2, l3, sBl + boff);
                #pragma unroll
                for (int i = 0; i < 4; i++) {
                    mma16816(acc[i][2*jp],   ah[i], h0, h1);
                    mma16816(acc[i][2*jp],   ah[i], l0, l1);
                    mma16816(acc[i][2*jp],   al[i], h0, h1);
                    mma16816(acc[i][2*jp+1], ah[i], h2, h3);
                    mma16816(acc[i][2*jp+1], ah[i], l2, l3);
                    mma16816(acc[i][2*jp+1], al[i], h2, h3);
                }
            }
        }
        __syncthreads();
    }

    // ---- epilogue: bias + scatter fp32 K/V and bf16 planes for Q/K/V ----
    #pragma unroll
    for (int i = 0; i < 4; i++) {
        #pragma unroll
        for (int eh = 0; eh < 2; eh++) {
            const int m = bm + wm*64 + i*16 + gr + eh*8;
            const int bb = m >> 11;
            const int s  = m & (SEQ - 1);
            #pragma unroll
            for (int j = 0; j < 4; j++) {
                const int n = bn + wn*32 + j*8 + qc*2;     // even
                const int t = n >> 10;
                const int hh = (n >> 6) & (NH - 1);
                const int d = n & (HD - 1);
                const float2 bv = *(const float2*)&bias[n];
                const float v0 = acc[i][j][2*eh]   + bv.x;
                const float v1 = acc[i][j][2*eh+1] + bv.y;
                const size_t idx = (((size_t)(bb*NH + hh))*SEQ + s)*HD + d;
                unsigned hp, lp; split_pack(v0, v1, hp, lp);
                if (t == 0) {
                    g_Qh[idx>>1] = hp; g_Ql[idx>>1] = lp;
                } else if (t == 1) {
                    *(float2*)&Kout[idx] = make_float2(v0, v1);
                    g_Kh[idx>>1] = hp; g_Kl[idx>>1] = lp;
                } else {
                    *(float2*)&Vout[idx] = make_float2(v0, v1);
                    g_Vh[idx>>1] = hp; g_Vl[idx>>1] = lp;
                }
            }
        }
    }
}

// ---------------------------------------------------------------------------
// Kernel 2: causal flash attention from bf16 planes.
// 4 warps, 64 q-rows/block, 64-key tiles. cp.async tiles, ldmatrix frags
// (V via ldmatrix.trans from row-major storage). bf16x3 MMA.
// ---------------------------------------------------------------------------
#define KST 72   // smem row stride (144B: LDSM conflict-free, 4-bank shift/row)

__global__ __launch_bounds__(128, 3)
void attn_tc(float* __restrict__ Out)
{
    __shared__ __align__(16) __nv_bfloat16 Kh_s[64][KST], Kl_s[64][KST];
    __shared__ __align__(16) __nv_bfloat16 Vh_s[64][KST], Vl_s[64][KST];

    const int bh = blockIdx.y;
    const int b = bh >> 4, h = bh & (NH - 1);
    const int qt = blockIdx.x;
    const int tid = threadIdx.x, w = tid >> 5, lane = tid & 31;
    const int gr = lane >> 2, qc = lane & 3;
    const int m0 = qt * 64 + w * 16;

    const unsigned sKh = smem_u32(&Kh_s[0][0]), sKl = smem_u32(&Kl_s[0][0]);
    const unsigned sVh = smem_u32(&Vh_s[0][0]), sVl = smem_u32(&Vl_s[0][0]);

    // Q fragments straight from planes (unscaled; S scaled later)
    unsigned qh[4][4], ql[4][4];
    const size_t qbase = (size_t)bh * SEQ;
    #pragma unroll
    for (int kk = 0; kk < 4; kk++) {
        #pragma unroll
        for (int e = 0; e < 4; e++) {
            const int r = m0 + gr + (e & 1) * 8;
            const int c = kk*16 + qc*2 + (e >> 1) * 8;
            qh[kk][e] = g_Qh[(qbase + r) * 32 + (c >> 1)];
            ql[kk][e] = g_Ql[(qbase + r) * 32 + (c >> 1)];
        }
    }

    float Oa[8][4];
    #pragma unroll
    for (int jd = 0; jd < 8; jd++)
        #pragma unroll
        for (int e = 0; e < 4; e++) Oa[jd][e] = 0.f;
    float mrow0 = -INFINITY, mrow1 = -INFINITY, lsum0 = 0.f, lsum1 = 0.f;

    const int lrow = tid >> 1;          // 0..63
    const int ch0  = (tid & 1) * 4;     // chunks 0-3 / 4-7

    for (int kt = 0; kt <= qt; kt++) {
        // ---- cp.async: 16 x 16B per thread (4 planes) ----
        const size_t rowb = (qbase + kt*64 + lrow) * 32;
        #pragma unroll
        for (int c = 0; c < 4; c++) {
            const int ch = ch0 + c;
            const unsigned doff = lrow * (KST*2) + ch * 16;
            cp16(sKh + doff, &g_Kh[rowb + ch*4]);
            cp16(sKl + doff, &g_Kl[rowb + ch*4]);
            cp16(sVh + doff, &g_Vh[rowb + ch*4]);
            cp16(sVl + doff, &g_Vl[rowb + ch*4]);
        }
        cp_commit_wait0();
        __syncthreads();

        // ---- S = Q K^T ----
        float S[8][4];
        #pragma unroll
        for (int j = 0; j < 8; j++)
            #pragma unroll
            for (int e = 0; e < 4; e++) S[j][e] = 0.f;

        const unsigned krow_f = ((lane >> 4) << 3) + (lane & 7);
        #pragma unroll
        for (int kk = 0; kk < 4; kk++) {
            const unsigned kcol = (kk*16 + ((lane >> 3) & 1) * 8) * 2;
            #pragma unroll
            for (int jp = 0; jp < 4; jp++) {
                const unsigned koff = (jp*16 + krow_f) * (KST*2) + kcol;
                unsigned h0,h1,h2,h3, l0,l1,l2,l3;
                ldsm_x4(h0, h1, h2, h3, sKh + koff);
                ldsm_x4(l0, l1, l2, l3, sKl + koff);
                mma16816(S[2*jp],   qh[kk], h0, h1);
                mma16816(S[2*jp],   qh[kk], l0, l1);
                mma16816(S[2*jp],   ql[kk], h0, h1);
                mma16816(S[2*jp+1], qh[kk], h2, h3);
                mma16816(S[2*jp+1], qh[kk], l2, l3);
                mma16816(S[2*jp+1], ql[kk], h2, h3);
            }
        }

        // scale (1/sqrt(HD))
        #pragma unroll
        for (int j = 0; j < 8; j++)
            #pragma unroll
            for (int e = 0; e < 4; e++) S[j][e] *= 0.125f;

        // ---- causal mask on diagonal tile ----
        if (kt == qt) {
            const int r0 = w*16 + gr, r1 = r0 + 8;
            #pragma unroll
            for (int j = 0; j < 8; j++) {
                const int cn = j*8 + qc*2;
                if (cn     > r0) S[j][0] = -1e30f;
                if (cn + 1 > r0) S[j][1] = -1e30f;
                if (cn     > r1) S[j][2] = -1e30f;
                if (cn + 1 > r1) S[j][3] = -1e30f;
            }
        }

        // ---- online softmax ----
        float mx0 = -1e30f, mx1 = -1e30f;
        #pragma unroll
        for (int j = 0; j < 8; j++) {
            mx0 = fmaxf(mx0, fmaxf(S[j][0], S[j][1]));
            mx1 = fmaxf(mx1, fmaxf(S[j][2], S[j][3]));
        }
        mx0 = fmaxf(mx0, __shfl_xor_sync(0xffffffff, mx0, 1));
        mx0 = fmaxf(mx0, __shfl_xor_sync(0xffffffff, mx0, 2));
        mx1 = fmaxf(mx1, __shfl_xor_sync(0xffffffff, mx1, 1));
        mx1 = fmaxf(mx1, __shfl_xor_sync(0xffffffff, mx1, 2));

        const float mnew0 = fmaxf(mrow0, mx0), mnew1 = fmaxf(mrow1, mx1);
        const float alpha0 = __expf(mrow0 - mnew0), alpha1 = __expf(mrow1 - mnew1);
        mrow0 = mnew0; mrow1 = mnew1;
        lsum0 *= alpha0; lsum1 *= alpha1;
        #pragma unroll
        for (int jd = 0; jd < 8; jd++) {
            Oa[jd][0] *= alpha0; Oa[jd][1] *= alpha0;
            Oa[jd][2] *= alpha1; Oa[jd][3] *= alpha1;
        }

        float rs0 = 0.f, rs1 = 0.f;
        #pragma unroll
        for (int j = 0; j < 8; j++) {
            S[j][0] = __expf(S[j][0] - mnew0);
            S[j][1] = __expf(S[j][1] - mnew0);
            S[j][2] = __expf(S[j][2] - mnew1);
            S[j][3] = __expf(S[j][3] - mnew1);
            rs0 += S[j][0] + S[j][1];
            rs1 += S[j][2] + S[j][3];
        }
        rs0 += __shfl_xor_sync(0xffffffff, rs0, 1);
        rs0 += __shfl_xor_sync(0xffffffff, rs0, 2);
        rs1 += __shfl_xor_sync(0xffffffff, rs1, 1);
        rs1 += __shfl_xor_sync(0xffffffff, rs1, 2);
        lsum0 += rs0; lsum1 += rs1;

        // ---- O += P V (V frags via ldmatrix.trans on row-major V) ----
        #pragma unroll
        for (int kk = 0; kk < 4; kk++) {
            unsigned ph[4], pl[4];
            const int j0 = kk*2, j1 = kk*2 + 1;
            split_pack(S[j0][0], S[j0][1], ph[0], pl[0]);
            split_pack(S[j0][2], S[j0][3], ph[1], pl[1]);
            split_pack(S[j1][0], S[j1][1], ph[2], pl[2]);
            split_pack(S[j1][2], S[j1][3], ph[3], pl[3]);
            const unsigned vrow = (kk*16 + (lane & 15)) * (KST*2);
            const unsigned vcolb = (lane >> 4) * 16;   // (lane>>4)*8 elems * 2B
            #pragma unroll
            for (int jp = 0; jp < 4; jp++) {
                const unsigned voff = vrow + jp*32 + vcolb;
                unsigned vh0,vh1,vh2,vh3, vl0,vl1,vl2,vl3;
                ldsm_x4_t(vh0, vh1, vh2, vh3, sVh + voff);
                ldsm_x4_t(vl0, vl1, vl2, vl3, sVl + voff);
                mma16816(Oa[2*jp],   ph, vh0, vh1);
                mma16816(Oa[2*jp],   ph, vl0, vl1);
                mma16816(Oa[2*jp],   pl, vh0, vh1);
                mma16816(Oa[2*jp+1], ph, vh2, vh3);
                mma16816(Oa[2*jp+1], ph, vl2, vl3);
                mma16816(Oa[2*jp+1], pl, vh2, vh3);
            }
        }
        __syncthreads();
    }

    // ---- normalize + write [b, s, h*64+d] ----
    const float inv0 = 1.f / lsum0, inv1 = 1.f / lsum1;
    float* Op = Out + ((size_t)b * SEQ + m0) * DMODEL + h * HD;
    #pragma unroll
    for (int jd = 0; jd < 8; jd++) {
        const int c = jd*8 + qc*2;
        float2 v0; v0.x = Oa[jd][0] * inv0; v0.y = Oa[jd][1] * inv0;
        float2 v1; v1.x = Oa[jd][2] * inv1; v1.y = Oa[jd][3] * inv1;
        *(float2*)&Op[(size_t)gr * DMODEL + c]       = v0;
        *(float2*)&Op[(size_t)(gr + 8) * DMODEL + c] = v1;
    }
}

// ---------------------------------------------------------------------------
extern "C" void kernel_launch(void* const* d_in, const int* in_sizes, int n_in,
                              void* d_out, int out_size)
{
    const float* X    = (const float*)d_in[0];
    const float* Wqkv = (const float*)d_in[1];
    const float* bqkv = (const float*)d_in[2];

    float* out  = (float*)d_out;
    float* Kout = (float*)d_out + ELEMS;
    float* Vout = (float*)d_out + 2 * (size_t)ELEMS;

    convert_planes<<<512, 256>>>((const float4*)X, (const float4*)Wqkv);

    dim3 ggrid(N_GEMM / 128, M_GEMM / 128);   // (24, 32)
    qkv_gemm_tc<<<ggrid, 256>>>(bqkv, Kout, Vout);

    dim3 agrid(SEQ / 64, BS * NH);            // (32, 32)
    attn_tc<<<agrid, 128>>>(out);
}

// round 6
// speedup vs baseline: 3.1749x; 1.0244x over previous
#include <cuda_runtime.h>
#include <cuda_bf16.h>
#include <math.h>

#define BS   2
#define SEQ  2048
#define DMODEL 1024
#define NH   16
#define HD   64
#define M_GEMM 4096
#define N_GEMM 3072
#define K_GEMM 1024
#define ELEMS (BS*SEQ*DMODEL)

// bf16 hi/lo planes (packed pairs as unsigned). Device globals => no allocation.
__device__ unsigned g_Xh[M_GEMM*K_GEMM/2], g_Xl[M_GEMM*K_GEMM/2];
__device__ unsigned g_Wh[N_GEMM*K_GEMM/2], g_Wl[N_GEMM*K_GEMM/2];
__device__ unsigned g_Qh[ELEMS/2], g_Ql[ELEMS/2];   // Q pre-scaled by 0.125
__device__ unsigned g_Kh[ELEMS/2], g_Kl[ELEMS/2];
__device__ unsigned g_Vh[ELEMS/2], g_Vl[ELEMS/2];

// ---------------------------------------------------------------------------
// helpers
// ---------------------------------------------------------------------------
__device__ __forceinline__ unsigned pack_bf16(float a, float b) {
    __nv_bfloat162 t; t.x = __float2bfloat16_rn(a); t.y = __float2bfloat16_rn(b);
    return *reinterpret_cast<unsigned*>(&t);
}
__device__ __forceinline__ void split_pack(float a, float b, unsigned& h, unsigned& l) {
    __nv_bfloat16 ah = __float2bfloat16_rn(a);
    __nv_bfloat16 bh = __float2bfloat16_rn(b);
    __nv_bfloat162 hv; hv.x = ah; hv.y = bh;
    h = *reinterpret_cast<unsigned*>(&hv);
    l = pack_bf16(a - __bfloat162float(ah), b - __bfloat162float(bh));
}
__device__ __forceinline__ void mma16816(float* d, const unsigned* a, unsigned b0, unsigned b1) {
    asm volatile(
        "mma.sync.aligned.m16n8k16.row.col.f32.bf16.bf16.f32 "
        "{%0,%1,%2,%3}, {%4,%5,%6,%7}, {%8,%9}, {%0,%1,%2,%3};"
        : "+f"(d[0]), "+f"(d[1]), "+f"(d[2]), "+f"(d[3])
        : "r"(a[0]), "r"(a[1]), "r"(a[2]), "r"(a[3]), "r"(b0), "r"(b1));
}
__device__ __forceinline__ unsigned smem_u32(const void* p) {
    return (unsigned)__cvta_generic_to_shared(p);
}
__device__ __forceinline__ void ldsm_x4(unsigned& r0, unsigned& r1, unsigned& r2, unsigned& r3, unsigned addr) {
    asm volatile("ldmatrix.sync.aligned.m8n8.x4.shared.b16 {%0,%1,%2,%3}, [%4];"
                 : "=r"(r0), "=r"(r1), "=r"(r2), "=r"(r3) : "r"(addr));
}
__device__ __forceinline__ void ldsm_x4_t(unsigned& r0, unsigned& r1, unsigned& r2, unsigned& r3, unsigned addr) {
    asm volatile("ldmatrix.sync.aligned.m8n8.x4.trans.shared.b16 {%0,%1,%2,%3}, [%4];"
                 : "=r"(r0), "=r"(r1), "=r"(r2), "=r"(r3) : "r"(addr));
}
__device__ __forceinline__ void cp16(unsigned dst, const void* src) {
    asm volatile("cp.async.cg.shared.global [%0], [%1], 16;" :: "r"(dst), "l"(src));
}
__device__ __forceinline__ void cp_commit() {
    asm volatile("cp.async.commit_group;" ::: "memory");
}
__device__ __forceinline__ void cp_wait0() {
    asm volatile("cp.async.wait_group 0;" ::: "memory");
}
__device__ __forceinline__ void cp_wait1() {
    asm volatile("cp.async.wait_group 1;" ::: "memory");
}

// ---------------------------------------------------------------------------
// Kernel 0: split X, W into bf16 hi/lo planes
// ---------------------------------------------------------------------------
__global__ void convert_planes(const float4* __restrict__ X4, const float4* __restrict__ W4)
{
    const int i0 = blockIdx.x * blockDim.x + threadIdx.x;
    const int stride = gridDim.x * blockDim.x;
    for (int idx = i0; idx < M_GEMM * K_GEMM / 4; idx += stride) {
        float4 v = X4[idx];
        unsigned h0, l0, h1, l1;
        split_pack(v.x, v.y, h0, l0); split_pack(v.z, v.w, h1, l1);
        g_Xh[2*idx] = h0; g_Xh[2*idx+1] = h1;
        g_Xl[2*idx] = l0; g_Xl[2*idx+1] = l1;
    }
    for (int idx = i0; idx < N_GEMM * K_GEMM / 4; idx += stride) {
        float4 v = W4[idx];
        unsigned h0, l0, h1, l1;
        split_pack(v.x, v.y, h0, l0); split_pack(v.z, v.w, h1, l1);
        g_Wh[2*idx] = h0; g_Wh[2*idx+1] = h1;
        g_Wl[2*idx] = l0; g_Wl[2*idx+1] = l1;
    }
}

// ---------------------------------------------------------------------------
// Kernel 1: QKV GEMM, 2-stage cp.async pipeline, ldmatrix frags, bf16x3 MMA.
// 128x128 tile, BK=32, 256 threads = 8 warps (2m x 4n).
// Dynamic smem: 2 stages x 4 planes x 128 x GST bf16.
// ---------------------------------------------------------------------------
#define GST 40                         // smem row stride (80B)
#define PS_G (128*GST*2)               // plane bytes 10240
#define STG_G (4*PS_G)                 // stage bytes 40960

extern __shared__ __align__(16) char dynsmem[];

__global__ __launch_bounds__(256, 2)
void qkv_gemm_tc(const float* __restrict__ bias,
                 float* __restrict__ Kout, float* __restrict__ Vout)
{
    const int tid = threadIdx.x;
    const int w = tid >> 5, lane = tid & 31;
    const int wm = w & 1, wn = w >> 1;
    const int gr = lane >> 2, qc = lane & 3;
    const int bm = blockIdx.y * 128, bn = blockIdx.x * 128;

    const unsigned sbase = smem_u32(dynsmem);
    const int lrow = tid >> 1;               // 0..127
    const int ch0  = (tid & 1) * 2;          // chunk 0/2

    const size_t arow0 = (size_t)(bm + lrow) * (K_GEMM/2);
    const size_t brow0 = (size_t)(bn + lrow) * (K_GEMM/2);
    const unsigned doff_base = lrow * (GST*2);

    // stage loader: k-block index kb (0..31), stage s
    auto issue_load = [&](int kb, int s) {
        const unsigned st = sbase + s * STG_G;
        const size_t ar = arow0 + kb * 16;
        const size_t br = brow0 + kb * 16;
        #pragma unroll
        for (int c = 0; c < 2; c++) {
            const int ch = ch0 + c;
            const unsigned doff = doff_base + ch * 16;
            cp16(st            + doff, &g_Xh[ar + ch*4]);
            cp16(st + PS_G     + doff, &g_Xl[ar + ch*4]);
            cp16(st + 2*PS_G   + doff, &g_Wh[br + ch*4]);
            cp16(st + 3*PS_G   + doff, &g_Wl[br + ch*4]);
        }
    };

    float acc[4][4][4];
    #pragma unroll
    for (int i = 0; i < 4; i++)
        #pragma unroll
        for (int j = 0; j < 4; j++)
            #pragma unroll
            for (int e = 0; e < 4; e++) acc[i][j][e] = 0.f;

    issue_load(0, 0); cp_commit();

    const unsigned acol_b = (lane >> 4) * 16;            // bytes
    const unsigned arow_f = (lane & 15);
    const unsigned bcol_b = ((lane >> 3) & 1) * 16;
    const unsigned brow_f = ((lane >> 4) << 3) + (lane & 7);

    #pragma unroll 1
    for (int kb = 0; kb < 32; kb++) {
        const int cur = kb & 1;
        if (kb < 31) { issue_load(kb + 1, cur ^ 1); cp_commit(); cp_wait1(); }
        else cp_wait0();
        __syncthreads();

        const unsigned sAh = sbase + cur * STG_G;
        const unsigned sAl = sAh + PS_G;
        const unsigned sBh = sAh + 2*PS_G;
        const unsigned sBl = sAh + 3*PS_G;

        #pragma unroll
        for (int kt = 0; kt < 2; kt++) {
            unsigned ah[4][4], al[4][4];
            const unsigned acol = kt*32 + acol_b;
            #pragma unroll
            for (int i = 0; i < 4; i++) {
                const unsigned aoff = (unsigned)(wm*64 + i*16 + arow_f) * (GST*2) + acol;
                ldsm_x4(ah[i][0], ah[i][1], ah[i][2], ah[i][3], sAh + aoff);
                ldsm_x4(al[i][0], al[i][1], al[i][2], al[i][3], sAl + aoff);
            }
            const unsigned bcol = kt*32 + bcol_b;
            #pragma unroll
            for (int jp = 0; jp < 2; jp++) {
                const unsigned boff = (unsigned)(wn*32 + jp*16 + brow_f) * (GST*2) + bcol;
                unsigned h0,h1,h2,h3, l0,l1,l2,l3;
                ldsm_x4(h0, h1, h2, h3, sBh + boff);
                ldsm_x4(l0, l1, l2, l3, sBl + boff);
                #pragma unroll
                for (int i = 0; i < 4; i++) {
                    mma16816(acc[i][2*jp],   ah[i], h0, h1);
                    mma16816(acc[i][2*jp],   ah[i], l0, l1);
                    mma16816(acc[i][2*jp],   al[i], h0, h1);
                    mma16816(acc[i][2*jp+1], ah[i], h2, h3);
                    mma16816(acc[i][2*jp+1], ah[i], l2, l3);
                    mma16816(acc[i][2*jp+1], al[i], h2, h3);
                }
            }
        }
        __syncthreads();
    }

    // ---- epilogue: bias + scatter fp32 K/V + bf16 planes (Q pre-scaled) ----
    #pragma unroll
    for (int i = 0; i < 4; i++) {
        #pragma unroll
        for (int eh = 0; eh < 2; eh++) {
            const int m = bm + wm*64 + i*16 + gr + eh*8;
            const int bb = m >> 11;
            const int s  = m & (SEQ - 1);
            #pragma unroll
            for (int j = 0; j < 4; j++) {
                const int n = bn + wn*32 + j*8 + qc*2;     // even
                const int t = n >> 10;
                const int hh = (n >> 6) & (NH - 1);
                const int d = n & (HD - 1);
                const float2 bv = *(const float2*)&bias[n];
                const float v0 = acc[i][j][2*eh]   + bv.x;
                const float v1 = acc[i][j][2*eh+1] + bv.y;
                const size_t idx = (((size_t)(bb*NH + hh))*SEQ + s)*HD + d;
                if (t == 0) {
                    unsigned hp, lp; split_pack(v0 * 0.125f, v1 * 0.125f, hp, lp);
                    g_Qh[idx>>1] = hp; g_Ql[idx>>1] = lp;
                } else if (t == 1) {
                    unsigned hp, lp; split_pack(v0, v1, hp, lp);
                    *(float2*)&Kout[idx] = make_float2(v0, v1);
                    g_Kh[idx>>1] = hp; g_Kl[idx>>1] = lp;
                } else {
                    unsigned hp, lp; split_pack(v0, v1, hp, lp);
                    *(float2*)&Vout[idx] = make_float2(v0, v1);
                    g_Vh[idx>>1] = hp; g_Vl[idx>>1] = lp;
                }
            }
        }
    }
}

// ---------------------------------------------------------------------------
// Kernel 2: causal flash attention, 2-stage cp.async pipeline, bf16x3 MMA.
// 4 warps, 64 q-rows/block, 64-key tiles.
// Dynamic smem: 2 stages x 4 planes x 64 x KST bf16.
// ---------------------------------------------------------------------------
#define KST 72                         // smem row stride (144B)
#define PS_A (64*KST*2)                // plane bytes 9216
#define STG_A (4*PS_A)                 // stage bytes 36864

__global__ __launch_bounds__(128, 3)
void attn_tc(float* __restrict__ Out)
{
    const int bh = blockIdx.y;
    const int b = bh >> 4, h = bh & (NH - 1);
    const int qt = blockIdx.x;
    const int tid = threadIdx.x, w = tid >> 5, lane = tid & 31;
    const int gr = lane >> 2, qc = lane & 3;
    const int m0 = qt * 64 + w * 16;

    const unsigned sbase = smem_u32(dynsmem);
    const size_t qbase = (size_t)bh * SEQ;

    // Q fragments from pre-scaled planes
    unsigned qh[4][4], ql[4][4];
    #pragma unroll
    for (int kk = 0; kk < 4; kk++) {
        #pragma unroll
        for (int e = 0; e < 4; e++) {
            const int r = m0 + gr + (e & 1) * 8;
            const int c = kk*16 + qc*2 + (e >> 1) * 8;
            qh[kk][e] = g_Qh[(qbase + r) * 32 + (c >> 1)];
            ql[kk][e] = g_Ql[(qbase + r) * 32 + (c >> 1)];
        }
    }

    float Oa[8][4];
    #pragma unroll
    for (int jd = 0; jd < 8; jd++)
        #pragma unroll
        for (int e = 0; e < 4; e++) Oa[jd][e] = 0.f;
    float mrow0 = -INFINITY, mrow1 = -INFINITY, lsum0 = 0.f, lsum1 = 0.f;

    const int lrow = tid >> 1;          // 0..63
    const int ch0  = (tid & 1) * 4;     // chunks 0-3 / 4-7
    const unsigned doff_base = lrow * (KST*2);

    auto issue_load = [&](int kt, int s) {
        const unsigned st = sbase + s * STG_A;
        const size_t rowb = (qbase + kt*64 + lrow) * 32;
        #pragma unroll
        for (int c = 0; c < 4; c++) {
            const int ch = ch0 + c;
            const unsigned doff = doff_base + ch * 16;
            cp16(st           + doff, &g_Kh[rowb + ch*4]);
            cp16(st + PS_A    + doff, &g_Kl[rowb + ch*4]);
            cp16(st + 2*PS_A  + doff, &g_Vh[rowb + ch*4]);
            cp16(st + 3*PS_A  + doff, &g_Vl[rowb + ch*4]);
        }
    };

    const unsigned krow_f = ((lane >> 4) << 3) + (lane & 7);
    const unsigned kcol_b = ((lane >> 3) & 1) * 16;
    const unsigned vrow_f = (lane & 15);
    const unsigned vcol_b = (lane >> 4) * 16;

    issue_load(0, 0); cp_commit();

    #pragma unroll 1
    for (int kt = 0; kt <= qt; kt++) {
        const int cur = kt & 1;
        if (kt < qt) { issue_load(kt + 1, cur ^ 1); cp_commit(); cp_wait1(); }
        else cp_wait0();
        __syncthreads();

        const unsigned sKh = sbase + cur * STG_A;
        const unsigned sKl = sKh + PS_A;
        const unsigned sVh = sKh + 2*PS_A;
        const unsigned sVl = sKh + 3*PS_A;

        // ---- S = Q K^T (pre-scaled Q) ----
        float S[8][4];
        #pragma unroll
        for (int j = 0; j < 8; j++)
            #pragma unroll
            for (int e = 0; e < 4; e++) S[j][e] = 0.f;

        #pragma unroll
        for (int kk = 0; kk < 4; kk++) {
            const unsigned kcol = kk*32 + kcol_b;
            #pragma unroll
            for (int jp = 0; jp < 4; jp++) {
                const unsigned koff = (jp*16 + krow_f) * (KST*2) + kcol;
                unsigned h0,h1,h2,h3, l0,l1,l2,l3;
                ldsm_x4(h0, h1, h2, h3, sKh + koff);
                ldsm_x4(l0, l1, l2, l3, sKl + koff);
                mma16816(S[2*jp],   qh[kk], h0, h1);
                mma16816(S[2*jp],   qh[kk], l0, l1);
                mma16816(S[2*jp],   ql[kk], h0, h1);
                mma16816(S[2*jp+1], qh[kk], h2, h3);
                mma16816(S[2*jp+1], qh[kk], l2, l3);
                mma16816(S[2*jp+1], ql[kk], h2, h3);
            }
        }

        // ---- causal mask on diagonal tile ----
        if (kt == qt) {
            const int r0 = w*16 + gr, r1 = r0 + 8;
            #pragma unroll
            for (int j = 0; j < 8; j++) {
                const int cn = j*8 + qc*2;
                if (cn     > r0) S[j][0] = -1e30f;
                if (cn + 1 > r0) S[j][1] = -1e30f;
                if (cn     > r1) S[j][2] = -1e30f;
                if (cn + 1 > r1) S[j][3] = -1e30f;
            }
        }

        // ---- online softmax ----
        float mx0 = -1e30f, mx1 = -1e30f;
        #pragma unroll
        for (int j = 0; j < 8; j++) {
            mx0 = fmaxf(mx0, fmaxf(S[j][0], S[j][1]));
            mx1 = fmaxf(mx1, fmaxf(S[j][2], S[j][3]));
        }
        mx0 = fmaxf(mx0, __shfl_xor_sync(0xffffffff, mx0, 1));
        mx0 = fmaxf(mx0, __shfl_xor_sync(0xffffffff, mx0, 2));
        mx1 = fmaxf(mx1, __shfl_xor_sync(0xffffffff, mx1, 1));
        mx1 = fmaxf(mx1, __shfl_xor_sync(0xffffffff, mx1, 2));

        const float mnew0 = fmaxf(mrow0, mx0), mnew1 = fmaxf(mrow1, mx1);
        const float alpha0 = __expf(mrow0 - mnew0), alpha1 = __expf(mrow1 - mnew1);
        mrow0 = mnew0; mrow1 = mnew1;
        lsum0 *= alpha0; lsum1 *= alpha1;
        #pragma unroll
        for (int jd = 0; jd < 8; jd++) {
            Oa[jd][0] *= alpha0; Oa[jd][1] *= alpha0;
            Oa[jd][2] *= alpha1; Oa[jd][3] *= alpha1;
        }

        float rs0 = 0.f, rs1 = 0.f;
        #pragma unroll
        for (int j = 0; j < 8; j++) {
            S[j][0] = __expf(S[j][0] - mnew0);
            S[j][1] = __expf(S[j][1] - mnew0);
            S[j][2] = __expf(S[j][2] - mnew1);
            S[j][3] = __expf(S[j][3] - mnew1);
            rs0 += S[j][0] + S[j][1];
            rs1 += S[j][2] + S[j][3];
        }
        rs0 += __shfl_xor_sync(0xffffffff, rs0, 1);
        rs0 += __shfl_xor_sync(0xffffffff, rs0, 2);
        rs1 += __shfl_xor_sync(0xffffffff, rs1, 1);
        rs1 += __shfl_xor_sync(0xffffffff, rs1, 2);
        lsum0 += rs0; lsum1 += rs1;

        // ---- O += P V ----
        #pragma unroll
        for (int kk = 0; kk < 4; kk++) {
            unsigned ph[4], pl[4];
            const int j0 = kk*2, j1 = kk*2 + 1;
            split_pack(S[j0][0], S[j0][1], ph[0], pl[0]);
            split_pack(S[j0][2], S[j0][3], ph[1], pl[1]);
            split_pack(S[j1][0], S[j1][1], ph[2], pl[2]);
            split_pack(S[j1][2], S[j1][3], ph[3], pl[3]);
            const unsigned vrow = (kk*16 + vrow_f) * (KST*2);
            #pragma unroll
            for (int jp = 0; jp < 4; jp++) {
                const unsigned voff = vrow + jp*32 + vcol_b;
                unsigned vh0,vh1,vh2,vh3, vl0,vl1,vl2,vl3;
                ldsm_x4_t(vh0, vh1, vh2, vh3, sVh + voff);
                ldsm_x4_t(vl0, vl1, vl2, vl3, sVl + voff);
                mma16816(Oa[2*jp],   ph, vh0, vh1);
                mma16816(Oa[2*jp],   ph, vl0, vl1);
                mma16816(Oa[2*jp],   pl, vh0, vh1);
                mma16816(Oa[2*jp+1], ph, vh2, vh3);
                mma16816(Oa[2*jp+1], ph, vl2, vl3);
                mma16816(Oa[2*jp+1], pl, vh2, vh3);
            }
        }
        __syncthreads();
    }

    // ---- normalize + write [b, s, h*64+d] ----
    const float inv0 = 1.f / lsum0, inv1 = 1.f / lsum1;
    float* Op = Out + ((size_t)b * SEQ + m0) * DMODEL + h * HD;
    #pragma unroll
    for (int jd = 0; jd < 8; jd++) {
        const int c = jd*8 + qc*2;
        float2 v0; v0.x = Oa[jd][0] * inv0; v0.y = Oa[jd][1] * inv0;
        float2 v1; v1.x = Oa[jd][2] * inv1; v1.y = Oa[jd][3] * inv1;
        *(float2*)&Op[(size_t)gr * DMODEL + c]       = v0;
        *(float2*)&Op[(size_t)(gr + 8) * DMODEL + c] = v1;
    }
}

// ---------------------------------------------------------------------------
extern "C" void kernel_launch(void* const* d_in, const int* in_sizes, int n_in,
                              void* d_out, int out_size)
{
    const float* X    = (const float*)d_in[0];
    const float* Wqkv = (const float*)d_in[1];
    const float* bqkv = (const float*)d_in[2];

    float* out  = (float*)d_out;
    float* Kout = (float*)d_out + ELEMS;
    float* Vout = (float*)d_out + 2 * (size_t)ELEMS;

    static bool attr_done = false;
    if (!attr_done) {
        cudaFuncSetAttribute(qkv_gemm_tc, cudaFuncAttributeMaxDynamicSharedMemorySize, 2 * STG_G);
        cudaFuncSetAttribute(attn_tc,     cudaFuncAttributeMaxDynamicSharedMemorySize, 2 * STG_A);
        attr_done = true;
    }

    convert_planes<<<512, 256>>>((const float4*)X, (const float4*)Wqkv);

    dim3 ggrid(N_GEMM / 128, M_GEMM / 128);   // (24, 32)
    qkv_gemm_tc<<<ggrid, 256, 2 * STG_G>>>(bqkv, Kout, Vout);

    dim3 agrid(SEQ / 64, BS * NH);            // (32, 32)
    attn_tc<<<agrid, 128, 2 * STG_A>>>(out);
}

// round 8
// speedup vs baseline: 4.0314x; 1.2698x over previous
#include <cuda_runtime.h>
#include <cuda_fp16.h>
#include <math.h>

#define BS   2
#define SEQ  2048
#define DMODEL 1024
#define NH   16
#define HD   64
#define M_GEMM 4096
#define N_GEMM 3072
#define K_GEMM 1024
#define ELEMS (BS*SEQ*DMODEL)

// fp16 planes (packed pairs as unsigned). Device globals => no allocation.
__device__ unsigned g_Xh[M_GEMM*K_GEMM/2];                    // X hi only
__device__ unsigned g_Wh[N_GEMM*K_GEMM/2], g_Wl[N_GEMM*K_GEMM/2];  // W*64 hi/lo
__device__ unsigned g_Qh[ELEMS/2];                            // Q * 0.125*log2e, hi only
__device__ unsigned g_Kh[ELEMS/2], g_Kl[ELEMS/2];
__device__ unsigned g_Vh[ELEMS/2], g_Vl[ELEMS/2];

extern __shared__ __align__(16) char dynsmem[];

#define QSCALE (0.125f * 1.44269504088896f)   // fold 1/sqrt(64) and log2(e) into Q

// ---------------------------------------------------------------------------
// helpers
// ---------------------------------------------------------------------------
__device__ __forceinline__ unsigned pack_h(float a, float b) {
    __half2 t = __floats2half2_rn(a, b);
    return *reinterpret_cast<unsigned*>(&t);
}
__device__ __forceinline__ void split_pack_h(float a, float b, unsigned& h, unsigned& l) {
    __half ah = __float2half_rn(a);
    __half bh = __float2half_rn(b);
    __half2 hv; hv.x = ah; hv.y = bh;
    h = *reinterpret_cast<unsigned*>(&hv);
    l = pack_h(a - __half2float(ah), b - __half2float(bh));
}
__device__ __forceinline__ void mma16816(float* d, const unsigned* a, unsigned b0, unsigned b1) {
    asm volatile(
        "mma.sync.aligned.m16n8k16.row.col.f32.f16.f16.f32 "
        "{%0,%1,%2,%3}, {%4,%5,%6,%7}, {%8,%9}, {%0,%1,%2,%3};"
        : "+f"(d[0]), "+f"(d[1]), "+f"(d[2]), "+f"(d[3])
        : "r"(a[0]), "r"(a[1]), "r"(a[2]), "r"(a[3]), "r"(b0), "r"(b1));
}
__device__ __forceinline__ unsigned smem_u32(const void* p) {
    return (unsigned)__cvta_generic_to_shared(p);
}
__device__ __forceinline__ void ldsm_x4(unsigned& r0, unsigned& r1, unsigned& r2, unsigned& r3, unsigned addr) {
    asm volatile("ldmatrix.sync.aligned.m8n8.x4.shared.b16 {%0,%1,%2,%3}, [%4];"
                 : "=r"(r0), "=r"(r1), "=r"(r2), "=r"(r3) : "r"(addr));
}
__device__ __forceinline__ void ldsm_x4_t(unsigned& r0, unsigned& r1, unsigned& r2, unsigned& r3, unsigned addr) {
    asm volatile("ldmatrix.sync.aligned.m8n8.x4.trans.shared.b16 {%0,%1,%2,%3}, [%4];"
                 : "=r"(r0), "=r"(r1), "=r"(r2), "=r"(r3) : "r"(addr));
}
__device__ __forceinline__ void cp16(unsigned dst, const void* src) {
    asm volatile("cp.async.cg.shared.global [%0], [%1], 16;" :: "r"(dst), "l"(src));
}
__device__ __forceinline__ void cp_commit() { asm volatile("cp.async.commit_group;" ::: "memory"); }
__device__ __forceinline__ void cp_wait0() { asm volatile("cp.async.wait_group 0;" ::: "memory"); }
__device__ __forceinline__ void cp_wait1() { asm volatile("cp.async.wait_group 1;" ::: "memory"); }
__device__ __forceinline__ float ex2f(float x) {
    float r; asm("ex2.approx.f32 %0, %1;" : "=f"(r) : "f"(x)); return r;
}

// ---------------------------------------------------------------------------
// Kernel 0: X -> fp16 hi plane; W*64 -> fp16 hi/lo planes
// ---------------------------------------------------------------------------
__global__ void convert_planes(const float4* __restrict__ X4, const float4* __restrict__ W4)
{
    const int i0 = blockIdx.x * blockDim.x + threadIdx.x;
    const int stride = gridDim.x * blockDim.x;
    for (int idx = i0; idx < M_GEMM * K_GEMM / 4; idx += stride) {
        float4 v = X4[idx];
        g_Xh[2*idx]   = pack_h(v.x, v.y);
        g_Xh[2*idx+1] = pack_h(v.z, v.w);
    }
    for (int idx = i0; idx < N_GEMM * K_GEMM / 4; idx += stride) {
        float4 v = W4[idx];
        unsigned h0, l0, h1, l1;
        split_pack_h(v.x * 64.f, v.y * 64.f, h0, l0);
        split_pack_h(v.z * 64.f, v.w * 64.f, h1, l1);
        g_Wh[2*idx] = h0; g_Wh[2*idx+1] = h1;
        g_Wl[2*idx] = l0; g_Wl[2*idx+1] = l1;
    }
}

// ---------------------------------------------------------------------------
// Kernel 1: QKV GEMM, fp16 2-term (Xh*Wh + Xh*Wl), 2-stage cp.async pipeline.
// 128x128 tile, BK=32, 256 threads = 8 warps (2m x 4n).
// ---------------------------------------------------------------------------
#define GST 40                         // smem row stride (80B)
#define PS_G (128*GST*2)               // plane bytes 10240
#define STG_G (3*PS_G)                 // stage bytes 30720 (Ah, Bh, Bl)

__global__ __launch_bounds__(256, 2)
void qkv_gemm_tc(const float* __restrict__ bias,
                 float* __restrict__ Kout, float* __restrict__ Vout)
{
    const int tid = threadIdx.x;
    const int w = tid >> 5, lane = tid & 31;
    const int wm = w & 1, wn = w >> 1;
    const int gr = lane >> 2, qc = lane & 3;
    const int bm = blockIdx.y * 128, bn = blockIdx.x * 128;

    const unsigned sbase = smem_u32(dynsmem);
    const int lrow = tid >> 1;
    const int ch0  = (tid & 1) * 2;

    const size_t arow0 = (size_t)(bm + lrow) * (K_GEMM/2);
    const size_t brow0 = (size_t)(bn + lrow) * (K_GEMM/2);
    const unsigned doff_base = lrow * (GST*2);

    auto issue_load = [&](int kb, int s) {
        const unsigned st = sbase + s * STG_G;
        const size_t ar = arow0 + kb * 16;
        const size_t br = brow0 + kb * 16;
        #pragma unroll
        for (int c = 0; c < 2; c++) {
            const int ch = ch0 + c;
            const unsigned doff = doff_base + ch * 16;
            cp16(st          + doff, &g_Xh[ar + ch*4]);
            cp16(st + PS_G   + doff, &g_Wh[br + ch*4]);
            cp16(st + 2*PS_G + doff, &g_Wl[br + ch*4]);
        }
    };

    float acc[4][4][4];
    #pragma unroll
    for (int i = 0; i < 4; i++)
        #pragma unroll
        for (int j = 0; j < 4; j++)
            #pragma unroll
            for (int e = 0; e < 4; e++) acc[i][j][e] = 0.f;

    issue_load(0, 0); cp_commit();

    const unsigned acol_b = (lane >> 4) * 16;
    const unsigned arow_f = (lane & 15);
    const unsigned bcol_b = ((lane >> 3) & 1) * 16;
    const unsigned brow_f = ((lane >> 4) << 3) + (lane & 7);

    #pragma unroll 1
    for (int kb = 0; kb < 32; kb++) {
        const int cur = kb & 1;
        if (kb < 31) { issue_load(kb + 1, cur ^ 1); cp_commit(); cp_wait1(); }
        else cp_wait0();
        __syncthreads();

        const unsigned sAh = sbase + cur * STG_G;
        const unsigned sBh = sAh + PS_G;
        const unsigned sBl = sAh + 2*PS_G;

        #pragma unroll
        for (int kt = 0; kt < 2; kt++) {
            unsigned ah[4][4];
            const unsigned acol = kt*32 + acol_b;
            #pragma unroll
            for (int i = 0; i < 4; i++) {
                const unsigned aoff = (unsigned)(wm*64 + i*16 + arow_f) * (GST*2) + acol;
                ldsm_x4(ah[i][0], ah[i][1], ah[i][2], ah[i][3], sAh + aoff);
            }
            const unsigned bcol = kt*32 + bcol_b;
            #pragma unroll
            for (int jp = 0; jp < 2; jp++) {
                const unsigned boff = (unsigned)(wn*32 + jp*16 + brow_f) * (GST*2) + bcol;
                unsigned h0,h1,h2,h3, l0,l1,l2,l3;
                ldsm_x4(h0, h1, h2, h3, sBh + boff);
                ldsm_x4(l0, l1, l2, l3, sBl + boff);
                #pragma unroll
                for (int i = 0; i < 4; i++) {
                    mma16816(acc[i][2*jp],   ah[i], h0, h1);
                    mma16816(acc[i][2*jp],   ah[i], l0, l1);
                    mma16816(acc[i][2*jp+1], ah[i], h2, h3);
                    mma16816(acc[i][2*jp+1], ah[i], l2, l3);
                }
            }
        }
        __syncthreads();
    }

    // ---- epilogue: acc/64 + bias; scatter fp32 K/V + fp16 planes ----
    #pragma unroll
    for (int i = 0; i < 4; i++) {
        #pragma unroll
        for (int eh = 0; eh < 2; eh++) {
            const int m = bm + wm*64 + i*16 + gr + eh*8;
            const int bb = m >> 11;
            const int s  = m & (SEQ - 1);
            #pragma unroll
            for (int j = 0; j < 4; j++) {
                const int n = bn + wn*32 + j*8 + qc*2;     // even
                const int t = n >> 10;
                const int hh = (n >> 6) & (NH - 1);
                const int d = n & (HD - 1);
                const float2 bv = *(const float2*)&bias[n];
                const float v0 = acc[i][j][2*eh]   * 0.015625f + bv.x;
                const float v1 = acc[i][j][2*eh+1] * 0.015625f + bv.y;
                const size_t idx = (((size_t)(bb*NH + hh))*SEQ + s)*HD + d;
                if (t == 0) {
                    g_Qh[idx>>1] = pack_h(v0 * QSCALE, v1 * QSCALE);
                } else if (t == 1) {
                    unsigned hp, lp; split_pack_h(v0, v1, hp, lp);
                    *(float2*)&Kout[idx] = make_float2(v0, v1);
                    g_Kh[idx>>1] = hp; g_Kl[idx>>1] = lp;
                } else {
                    unsigned hp, lp; split_pack_h(v0, v1, hp, lp);
                    *(float2*)&Vout[idx] = make_float2(v0, v1);
                    g_Vh[idx>>1] = hp; g_Vl[idx>>1] = lp;
                }
            }
        }
    }
}

// ---------------------------------------------------------------------------
// Kernel 2: causal flash attention, fp16. S = Qh*(Kh+Kl) (2 MMAs/step),
// PV 3-term. Single-buffered smem, 4 blocks/SM, exp2-domain softmax.
// ---------------------------------------------------------------------------
#define KST 72
#define PS_A (64*KST*2)                // 9216
#define STG_A (4*PS_A)                 // 36864

__global__ __launch_bounds__(128, 4)
void attn_tc(float* __restrict__ Out)
{
    const int bh = blockIdx.y;
    const int b = bh >> 4, h = bh & (NH - 1);
    const int qt = gridDim.x - 1 - blockIdx.x;     // heavy blocks first
    const int tid = threadIdx.x, w = tid >> 5, lane = tid & 31;
    const int gr = lane >> 2, qc = lane & 3;
    const int m0 = qt * 64 + w * 16;

    const unsigned sbase = smem_u32(dynsmem);
    const size_t qbase = (size_t)bh * SEQ;

    // Q hi fragments only (pre-scaled by 0.125*log2e)
    unsigned qh[4][4];
    #pragma unroll
    for (int kk = 0; kk < 4; kk++) {
        #pragma unroll
        for (int e = 0; e < 4; e++) {
            const int r = m0 + gr + (e & 1) * 8;
            const int c = kk*16 + qc*2 + (e >> 1) * 8;
            qh[kk][e] = g_Qh[(qbase + r) * 32 + (c >> 1)];
        }
    }

    float Oa[8][4];
    #pragma unroll
    for (int jd = 0; jd < 8; jd++)
        #pragma unroll
        for (int e = 0; e < 4; e++) Oa[jd][e] = 0.f;
    float mrow0 = -INFINITY, mrow1 = -INFINITY, lsum0 = 0.f, lsum1 = 0.f;

    const int lrow = tid >> 1;
    const int ch0  = (tid & 1) * 4;
    const unsigned doff_base = lrow * (KST*2);

    const unsigned sKh = sbase;
    const unsigned sKl = sbase + PS_A;
    const unsigned sVh = sbase + 2*PS_A;
    const unsigned sVl = sbase + 3*PS_A;

    const unsigned krow_f = ((lane >> 4) << 3) + (lane & 7);
    const unsigned kcol_b = ((lane >> 3) & 1) * 16;
    const unsigned vrow_f = (lane & 15);
    const unsigned vcol_b = (lane >> 4) * 16;

    #pragma unroll 1
    for (int kt = 0; kt <= qt; kt++) {
        // ---- single-buffer load (cross-block overlap hides latency) ----
        const size_t rowb = (qbase + kt*64 + lrow) * 32;
        #pragma unroll
        for (int c = 0; c < 4; c++) {
            const int ch = ch0 + c;
            const unsigned doff = doff_base + ch * 16;
            cp16(sKh + doff, &g_Kh[rowb + ch*4]);
            cp16(sKl + doff, &g_Kl[rowb + ch*4]);
            cp16(sVh + doff, &g_Vh[rowb + ch*4]);
            cp16(sVl + doff, &g_Vl[rowb + ch*4]);
        }
        cp_commit(); cp_wait0();
        __syncthreads();

        // ---- S = Qh (Kh + Kl): 2 MMAs per fragment pair ----
        float S[8][4];
        #pragma unroll
        for (int j = 0; j < 8; j++)
            #pragma unroll
            for (int e = 0; e < 4; e++) S[j][e] = 0.f;

        #pragma unroll
        for (int kk = 0; kk < 4; kk++) {
            const unsigned kcol = kk*32 + kcol_b;
            #pragma unroll
            for (int jp = 0; jp < 4; jp++) {
                const unsigned koff = (jp*16 + krow_f) * (KST*2) + kcol;
                unsigned h0,h1,h2,h3, l0,l1,l2,l3;
                ldsm_x4(h0, h1, h2, h3, sKh + koff);
                ldsm_x4(l0, l1, l2, l3, sKl + koff);
                mma16816(S[2*jp],   qh[kk], h0, h1);
                mma16816(S[2*jp],   qh[kk], l0, l1);
                mma16816(S[2*jp+1], qh[kk], h2, h3);
                mma16816(S[2*jp+1], qh[kk], l2, l3);
            }
        }

        // ---- causal mask on diagonal tile ----
        if (kt == qt) {
            const int r0 = w*16 + gr, r1 = r0 + 8;
            #pragma unroll
            for (int j = 0; j < 8; j++) {
                const int cn = j*8 + qc*2;
                if (cn     > r0) S[j][0] = -1e30f;
                if (cn + 1 > r0) S[j][1] = -1e30f;
                if (cn     > r1) S[j][2] = -1e30f;
                if (cn + 1 > r1) S[j][3] = -1e30f;
            }
        }

        // ---- online softmax (base-2 domain) ----
        float mx0 = -1e30f, mx1 = -1e30f;
        #pragma unroll
        for (int j = 0; j < 8; j++) {
            mx0 = fmaxf(mx0, fmaxf(S[j][0], S[j][1]));
            mx1 = fmaxf(mx1, fmaxf(S[j][2], S[j][3]));
        }
        mx0 = fmaxf(mx0, __shfl_xor_sync(0xffffffff, mx0, 1));
        mx0 = fmaxf(mx0, __shfl_xor_sync(0xffffffff, mx0, 2));
        mx1 = fmaxf(mx1, __shfl_xor_sync(0xffffffff, mx1, 1));
        mx1 = fmaxf(mx1, __shfl_xor_sync(0xffffffff, mx1, 2));

        const float mnew0 = fmaxf(mrow0, mx0), mnew1 = fmaxf(mrow1, mx1);
        const float alpha0 = ex2f(mrow0 - mnew0), alpha1 = ex2f(mrow1 - mnew1);
        mrow0 = mnew0; mrow1 = mnew1;
        lsum0 *= alpha0; lsum1 *= alpha1;
        #pragma unroll
        for (int jd = 0; jd < 8; jd++) {
            Oa[jd][0] *= alpha0; Oa[jd][1] *= alpha0;
            Oa[jd][2] *= alpha1; Oa[jd][3] *= alpha1;
        }

        float rs0 = 0.f, rs1 = 0.f;
        #pragma unroll
        for (int j = 0; j < 8; j++) {
            S[j][0] = ex2f(S[j][0] - mnew0);
            S[j][1] = ex2f(S[j][1] - mnew0);
            S[j][2] = ex2f(S[j][2] - mnew1);
            S[j][3] = ex2f(S[j][3] - mnew1);
            rs0 += S[j][0] + S[j][1];
            rs1 += S[j][2] + S[j][3];
        }
        rs0 += __shfl_xor_sync(0xffffffff, rs0, 1);
        rs0 += __shfl_xor_sync(0xffffffff, rs0, 2);
        rs1 += __shfl_xor_sync(0xffffffff, rs1, 1);
        rs1 += __shfl_xor_sync(0xffffffff, rs1, 2);
        lsum0 += rs0; lsum1 += rs1;

        // ---- O += P V (3-term fp16) ----
        #pragma unroll
        for (int kk = 0; kk < 4; kk++) {
            unsigned pp[4], pl[4];
            const int j0 = kk*2, j1 = kk*2 + 1;
            split_pack_h(S[j0][0], S[j0][1], pp[0], pl[0]);
            split_pack_h(S[j0][2], S[j0][3], pp[1], pl[1]);
            split_pack_h(S[j1][0], S[j1][1], pp[2], pl[2]);
            split_pack_h(S[j1][2], S[j1][3], pp[3], pl[3]);
            const unsigned vrow = (kk*16 + vrow_f) * (KST*2);
            #pragma unroll
            for (int jp = 0; jp < 4; jp++) {
                const unsigned voff = vrow + jp*32 + vcol_b;
                unsigned vh0,vh1,vh2,vh3, vl0,vl1,vl2,vl3;
                ldsm_x4_t(vh0, vh1, vh2, vh3, sVh + voff);
                ldsm_x4_t(vl0, vl1, vl2, vl3, sVl + voff);
                mma16816(Oa[2*jp],   pp, vh0, vh1);
                mma16816(Oa[2*jp],   pp, vl0, vl1);
                mma16816(Oa[2*jp],   pl, vh0, vh1);
                mma16816(Oa[2*jp+1], pp, vh2, vh3);
                mma16816(Oa[2*jp+1], pp, vl2, vl3);
                mma16816(Oa[2*jp+1], pl, vh2, vh3);
            }
        }
        __syncthreads();
    }

    const float inv0 = 1.f / lsum0, inv1 = 1.f / lsum1;
    float* Op = Out + ((size_t)b * SEQ + m0) * DMODEL + h * HD;
    #pragma unroll
    for (int jd = 0; jd < 8; jd++) {
        const int c = jd*8 + qc*2;
        float2 v0; v0.x = Oa[jd][0] * inv0; v0.y = Oa[jd][1] * inv0;
        float2 v1; v1.x = Oa[jd][2] * inv1; v1.y = Oa[jd][3] * inv1;
        *(float2*)&Op[(size_t)gr * DMODEL + c]       = v0;
        *(float2*)&Op[(size_t)(gr + 8) * DMODEL + c] = v1;
    }
}

// ---------------------------------------------------------------------------
extern "C" void kernel_launch(void* const* d_in, const int* in_sizes, int n_in,
                              void* d_out, int out_size)
{
    const float* X    = (const float*)d_in[0];
    const float* Wqkv = (const float*)d_in[1];
    const float* bqkv = (const float*)d_in[2];

    float* out  = (float*)d_out;
    float* Kout = (float*)d_out + ELEMS;
    float* Vout = (float*)d_out + 2 * (size_t)ELEMS;

    static bool attr_done = false;
    if (!attr_done) {
        cudaFuncSetAttribute(qkv_gemm_tc, cudaFuncAttributeMaxDynamicSharedMemorySize, 2 * STG_G);
        cudaFuncSetAttribute(attn_tc,     cudaFuncAttributeMaxDynamicSharedMemorySize, STG_A);
        attr_done = true;
    }

    convert_planes<<<512, 256>>>((const float4*)X, (const float4*)Wqkv);

    dim3 ggrid(N_GEMM / 128, M_GEMM / 128);   // (24, 32)
    qkv_gemm_tc<<<ggrid, 256, 2 * STG_G>>>(bqkv, Kout, Vout);

    dim3 agrid(SEQ / 64, BS * NH);            // (32, 32)
    attn_tc<<<agrid, 128, STG_A>>>(out);
}

// round 9
// speedup vs baseline: 4.0456x; 1.0035x over previous
#include <cuda_runtime.h>
#include <cuda_fp16.h>
#include <math.h>

#define BS   2
#define SEQ  2048
#define DMODEL 1024
#define NH   16
#define HD   64
#define M_GEMM 4096
#define N_GEMM 3072
#define K_GEMM 1024
#define ELEMS (BS*SEQ*DMODEL)

// fp16 planes (packed pairs as unsigned). Device globals => no allocation.
__device__ unsigned g_Xh[M_GEMM*K_GEMM/2];                    // X hi only
__device__ unsigned g_Wh[N_GEMM*K_GEMM/2], g_Wl[N_GEMM*K_GEMM/2];  // W*64 hi/lo
__device__ unsigned g_Qh[ELEMS/2];                            // Q * 0.125*log2e, hi only
__device__ unsigned g_Kh[ELEMS/2], g_Kl[ELEMS/2];
__device__ unsigned g_Vh[ELEMS/2], g_Vl[ELEMS/2];

extern __shared__ __align__(16) char dynsmem[];

#define QSCALE (0.125f * 1.44269504088896f)   // fold 1/sqrt(64) and log2(e) into Q

// ---------------------------------------------------------------------------
// helpers
// ---------------------------------------------------------------------------
__device__ __forceinline__ unsigned pack_h(float a, float b) {
    __half2 t = __floats2half2_rn(a, b);
    return *reinterpret_cast<unsigned*>(&t);
}
__device__ __forceinline__ void split_pack_h(float a, float b, unsigned& h, unsigned& l) {
    __half ah = __float2half_rn(a);
    __half bh = __float2half_rn(b);
    __half2 hv; hv.x = ah; hv.y = bh;
    h = *reinterpret_cast<unsigned*>(&hv);
    l = pack_h(a - __half2float(ah), b - __half2float(bh));
}
__device__ __forceinline__ void mma16816(float* d, const unsigned* a, unsigned b0, unsigned b1) {
    asm volatile(
        "mma.sync.aligned.m16n8k16.row.col.f32.f16.f16.f32 "
        "{%0,%1,%2,%3}, {%4,%5,%6,%7}, {%8,%9}, {%0,%1,%2,%3};"
        : "+f"(d[0]), "+f"(d[1]), "+f"(d[2]), "+f"(d[3])
        : "r"(a[0]), "r"(a[1]), "r"(a[2]), "r"(a[3]), "r"(b0), "r"(b1));
}
__device__ __forceinline__ unsigned smem_u32(const void* p) {
    return (unsigned)__cvta_generic_to_shared(p);
}
__device__ __forceinline__ void ldsm_x4(unsigned& r0, unsigned& r1, unsigned& r2, unsigned& r3, unsigned addr) {
    asm volatile("ldmatrix.sync.aligned.m8n8.x4.shared.b16 {%0,%1,%2,%3}, [%4];"
                 : "=r"(r0), "=r"(r1), "=r"(r2), "=r"(r3) : "r"(addr));
}
__device__ __forceinline__ void ldsm_x4_t(unsigned& r0, unsigned& r1, unsigned& r2, unsigned& r3, unsigned addr) {
    asm volatile("ldmatrix.sync.aligned.m8n8.x4.trans.shared.b16 {%0,%1,%2,%3}, [%4];"
                 : "=r"(r0), "=r"(r1), "=r"(r2), "=r"(r3) : "r"(addr));
}
__device__ __forceinline__ void cp16(unsigned dst, const void* src) {
    asm volatile("cp.async.cg.shared.global [%0], [%1], 16;" :: "r"(dst), "l"(src));
}
__device__ __forceinline__ void cp_commit() { asm volatile("cp.async.commit_group;" ::: "memory"); }
__device__ __forceinline__ void cp_wait0() { asm volatile("cp.async.wait_group 0;" ::: "memory"); }
__device__ __forceinline__ void cp_wait1() { asm volatile("cp.async.wait_group 1;" ::: "memory"); }
__device__ __forceinline__ float ex2f(float x) {
    float r; asm("ex2.approx.f32 %0, %1;" : "=f"(r) : "f"(x)); return r;
}

// ---------------------------------------------------------------------------
// Kernel 0: X -> fp16 hi plane; W*64 -> fp16 hi/lo planes
// ---------------------------------------------------------------------------
__global__ void convert_planes(const float4* __restrict__ X4, const float4* __restrict__ W4)
{
    const int i0 = blockIdx.x * blockDim.x + threadIdx.x;
    const int stride = gridDim.x * blockDim.x;
    for (int idx = i0; idx < M_GEMM * K_GEMM / 4; idx += stride) {
        float4 v = X4[idx];
        g_Xh[2*idx]   = pack_h(v.x, v.y);
        g_Xh[2*idx+1] = pack_h(v.z, v.w);
    }
    for (int idx = i0; idx < N_GEMM * K_GEMM / 4; idx += stride) {
        float4 v = W4[idx];
        unsigned h0, l0, h1, l1;
        split_pack_h(v.x * 64.f, v.y * 64.f, h0, l0);
        split_pack_h(v.z * 64.f, v.w * 64.f, h1, l1);
        g_Wh[2*idx] = h0; g_Wh[2*idx+1] = h1;
        g_Wl[2*idx] = l0; g_Wl[2*idx+1] = l1;
    }
}

// ---------------------------------------------------------------------------
// Kernel 1: QKV GEMM, fp16 2-term (Xh*Wh + Xh*Wl), 2-stage cp.async pipeline.
// 128x128 tile, BK=32, 256 threads = 8 warps (2m x 4n).
// ---------------------------------------------------------------------------
#define GST 40                         // smem row stride (80B)
#define PS_G (128*GST*2)               // plane bytes 10240
#define STG_G (3*PS_G)                 // stage bytes 30720 (Ah, Bh, Bl)

__global__ __launch_bounds__(256, 2)
void qkv_gemm_tc(const float* __restrict__ bias,
                 float* __restrict__ Kout, float* __restrict__ Vout)
{
    const int tid = threadIdx.x;
    const int w = tid >> 5, lane = tid & 31;
    const int wm = w & 1, wn = w >> 1;
    const int gr = lane >> 2, qc = lane & 3;
    const int bm = blockIdx.y * 128, bn = blockIdx.x * 128;

    const unsigned sbase = smem_u32(dynsmem);
    const int lrow = tid >> 1;
    const int ch0  = (tid & 1) * 2;

    const size_t arow0 = (size_t)(bm + lrow) * (K_GEMM/2);
    const size_t brow0 = (size_t)(bn + lrow) * (K_GEMM/2);
    const unsigned doff_base = lrow * (GST*2);

    auto issue_load = [&](int kb, int s) {
        const unsigned st = sbase + s * STG_G;
        const size_t ar = arow0 + kb * 16;
        const size_t br = brow0 + kb * 16;
        #pragma unroll
        for (int c = 0; c < 2; c++) {
            const int ch = ch0 + c;
            const unsigned doff = doff_base + ch * 16;
            cp16(st          + doff, &g_Xh[ar + ch*4]);
            cp16(st + PS_G   + doff, &g_Wh[br + ch*4]);
            cp16(st + 2*PS_G + doff, &g_Wl[br + ch*4]);
        }
    };

    float acc[4][4][4];
    #pragma unroll
    for (int i = 0; i < 4; i++)
        #pragma unroll
        for (int j = 0; j < 4; j++)
            #pragma unroll
            for (int e = 0; e < 4; e++) acc[i][j][e] = 0.f;

    issue_load(0, 0); cp_commit();

    const unsigned acol_b = (lane >> 4) * 16;
    const unsigned arow_f = (lane & 15);
    const unsigned bcol_b = ((lane >> 3) & 1) * 16;
    const unsigned brow_f = ((lane >> 4) << 3) + (lane & 7);

    #pragma unroll 1
    for (int kb = 0; kb < 32; kb++) {
        const int cur = kb & 1;
        if (kb < 31) { issue_load(kb + 1, cur ^ 1); cp_commit(); cp_wait1(); }
        else cp_wait0();
        __syncthreads();

        const unsigned sAh = sbase + cur * STG_G;
        const unsigned sBh = sAh + PS_G;
        const unsigned sBl = sAh + 2*PS_G;

        #pragma unroll
        for (int kt = 0; kt < 2; kt++) {
            unsigned ah[4][4];
            const unsigned acol = kt*32 + acol_b;
            #pragma unroll
            for (int i = 0; i < 4; i++) {
                const unsigned aoff = (unsigned)(wm*64 + i*16 + arow_f) * (GST*2) + acol;
                ldsm_x4(ah[i][0], ah[i][1], ah[i][2], ah[i][3], sAh + aoff);
            }
            const unsigned bcol = kt*32 + bcol_b;
            #pragma unroll
            for (int jp = 0; jp < 2; jp++) {
                const unsigned boff = (unsigned)(wn*32 + jp*16 + brow_f) * (GST*2) + bcol;
                unsigned h0,h1,h2,h3, l0,l1,l2,l3;
                ldsm_x4(h0, h1, h2, h3, sBh + boff);
                ldsm_x4(l0, l1, l2, l3, sBl + boff);
                #pragma unroll
                for (int i = 0; i < 4; i++) {
                    mma16816(acc[i][2*jp],   ah[i], h0, h1);
                    mma16816(acc[i][2*jp],   ah[i], l0, l1);
                    mma16816(acc[i][2*jp+1], ah[i], h2, h3);
                    mma16816(acc[i][2*jp+1], ah[i], l2, l3);
                }
            }
        }
        __syncthreads();
    }

    // ---- epilogue: acc/64 + bias; scatter fp32 K/V + fp16 planes ----
    #pragma unroll
    for (int i = 0; i < 4; i++) {
        #pragma unroll
        for (int eh = 0; eh < 2; eh++) {
            const int m = bm + wm*64 + i*16 + gr + eh*8;
            const int bb = m >> 11;
            const int s  = m & (SEQ - 1);
            #pragma unroll
            for (int j = 0; j < 4; j++) {
                const int n = bn + wn*32 + j*8 + qc*2;     // even
                const int t = n >> 10;
                const int hh = (n >> 6) & (NH - 1);
                const int d = n & (HD - 1);
                const float2 bv = *(const float2*)&bias[n];
                const float v0 = acc[i][j][2*eh]   * 0.015625f + bv.x;
                const float v1 = acc[i][j][2*eh+1] * 0.015625f + bv.y;
                const size_t idx = (((size_t)(bb*NH + hh))*SEQ + s)*HD + d;
                if (t == 0) {
                    g_Qh[idx>>1] = pack_h(v0 * QSCALE, v1 * QSCALE);
                } else if (t == 1) {
                    unsigned hp, lp; split_pack_h(v0, v1, hp, lp);
                    *(float2*)&Kout[idx] = make_float2(v0, v1);
                    g_Kh[idx>>1] = hp; g_Kl[idx>>1] = lp;
                } else {
                    unsigned hp, lp; split_pack_h(v0, v1, hp, lp);
                    *(float2*)&Vout[idx] = make_float2(v0, v1);
                    g_Vh[idx>>1] = hp; g_Vl[idx>>1] = lp;
                }
            }
        }
    }
}

// ---------------------------------------------------------------------------
// Kernel 2: causal flash attention, fp16. S = Qh*(Kh+Kl) (2 MMAs/step),
// PV 3-term. Single-buffered smem, 4 blocks/SM, exp2-domain softmax.
// ---------------------------------------------------------------------------
#define KST 72
#define PS_A (64*KST*2)                // 9216
#define STG_A (4*PS_A)                 // 36864

__global__ __launch_bounds__(128, 4)
void attn_tc(float* __restrict__ Out)
{
    const int bh = blockIdx.y;
    const int b = bh >> 4, h = bh & (NH - 1);
    const int qt = gridDim.x - 1 - blockIdx.x;     // heavy blocks first
    const int tid = threadIdx.x, w = tid >> 5, lane = tid & 31;
    const int gr = lane >> 2, qc = lane & 3;
    const int m0 = qt * 64 + w * 16;

    const unsigned sbase = smem_u32(dynsmem);
    const size_t qbase = (size_t)bh * SEQ;

    // Q hi fragments only (pre-scaled by 0.125*log2e)
    unsigned qh[4][4];
    #pragma unroll
    for (int kk = 0; kk < 4; kk++) {
        #pragma unroll
        for (int e = 0; e < 4; e++) {
            const int r = m0 + gr + (e & 1) * 8;
            const int c = kk*16 + qc*2 + (e >> 1) * 8;
            qh[kk][e] = g_Qh[(qbase + r) * 32 + (c >> 1)];
        }
    }

    float Oa[8][4];
    #pragma unroll
    for (int jd = 0; jd < 8; jd++)
        #pragma unroll
        for (int e = 0; e < 4; e++) Oa[jd][e] = 0.f;
    float mrow0 = -INFINITY, mrow1 = -INFINITY, lsum0 = 0.f, lsum1 = 0.f;

    const int lrow = tid >> 1;
    const int ch0  = (tid & 1) * 4;
    const unsigned doff_base = lrow * (KST*2);

    const unsigned sKh = sbase;
    const unsigned sKl = sbase + PS_A;
    const unsigned sVh = sbase + 2*PS_A;
    const unsigned sVl = sbase + 3*PS_A;

    const unsigned krow_f = ((lane >> 4) << 3) + (lane & 7);
    const unsigned kcol_b = ((lane >> 3) & 1) * 16;
    const unsigned vrow_f = (lane & 15);
    const unsigned vcol_b = (lane >> 4) * 16;

    #pragma unroll 1
    for (int kt = 0; kt <= qt; kt++) {
        // ---- single-buffer load (cross-block overlap hides latency) ----
        const size_t rowb = (qbase + kt*64 + lrow) * 32;
        #pragma unroll
        for (int c = 0; c < 4; c++) {
            const int ch = ch0 + c;
            const unsigned doff = doff_base + ch * 16;
            cp16(sKh + doff, &g_Kh[rowb + ch*4]);
            cp16(sKl + doff, &g_Kl[rowb + ch*4]);
            cp16(sVh + doff, &g_Vh[rowb + ch*4]);
            cp16(sVl + doff, &g_Vl[rowb + ch*4]);
        }
        cp_commit(); cp_wait0();
        __syncthreads();

        // ---- S = Qh (Kh + Kl): 2 MMAs per fragment pair ----
        float S[8][4];
        #pragma unroll
        for (int j = 0; j < 8; j++)
            #pragma unroll
            for (int e = 0; e < 4; e++) S[j][e] = 0.f;

        #pragma unroll
        for (int kk = 0; kk < 4; kk++) {
            const unsigned kcol = kk*32 + kcol_b;
            #pragma unroll
            for (int jp = 0; jp < 4; jp++) {
                const unsigned koff = (jp*16 + krow_f) * (KST*2) + kcol;
                unsigned h0,h1,h2,h3, l0,l1,l2,l3;
                ldsm_x4(h0, h1, h2, h3, sKh + koff);
                ldsm_x4(l0, l1, l2, l3, sKl + koff);
                mma16816(S[2*jp],   qh[kk], h0, h1);
                mma16816(S[2*jp],   qh[kk], l0, l1);
                mma16816(S[2*jp+1], qh[kk], h2, h3);
                mma16816(S[2*jp+1], qh[kk], l2, l3);
            }
        }

        // ---- causal mask on diagonal tile ----
        if (kt == qt) {
            const int r0 = w*16 + gr, r1 = r0 + 8;
            #pragma unroll
            for (int j = 0; j < 8; j++) {
                const int cn = j*8 + qc*2;
                if (cn     > r0) S[j][0] = -1e30f;
                if (cn + 1 > r0) S[j][1] = -1e30f;
                if (cn     > r1) S[j][2] = -1e30f;
                if (cn + 1 > r1) S[j][3] = -1e30f;
            }
        }

        // ---- online softmax (base-2 domain) ----
        float mx0 = -1e30f, mx1 = -1e30f;
        #pragma unroll
        for (int j = 0; j < 8; j++) {
            mx0 = fmaxf(mx0, fmaxf(S[j][0], S[j][1]));
            mx1 = fmaxf(mx1, fmaxf(S[j][2], S[j][3]));
        }
        mx0 = fmaxf(mx0, __shfl_xor_sync(0xffffffff, mx0, 1));
        mx0 = fmaxf(mx0, __shfl_xor_sync(0xffffffff, mx0, 2));
        mx1 = fmaxf(mx1, __shfl_xor_sync(0xffffffff, mx1, 1));
        mx1 = fmaxf(mx1, __shfl_xor_sync(0xffffffff, mx1, 2));

        const float mnew0 = fmaxf(mrow0, mx0), mnew1 = fmaxf(mrow1, mx1);
        const float alpha0 = ex2f(mrow0 - mnew0), alpha1 = ex2f(mrow1 - mnew1);
        mrow0 = mnew0; mrow1 = mnew1;
        lsum0 *= alpha0; lsum1 *= alpha1;
        #pragma unroll
        for (int jd = 0; jd < 8; jd++) {
            Oa[jd][0] *= alpha0; Oa[jd][1] *= alpha0;
            Oa[jd][2] *= alpha1; Oa[jd][3] *= alpha1;
        }

        float rs0 = 0.f, rs1 = 0.f;
        #pragma unroll
        for (int j = 0; j < 8; j++) {
            S[j][0] = ex2f(S[j][0] - mnew0);
            S[j][1] = ex2f(S[j][1] - mnew0);
            S[j][2] = ex2f(S[j][2] - mnew1);
            S[j][3] = ex2f(S[j][3] - mnew1);
            rs0 += S[j][0] + S[j][1];
            rs1 += S[j][2] + S[j][3];
        }
        rs0 += __shfl_xor_sync(0xffffffff, rs0, 1);
        rs0 += __shfl_xor_sync(0xffffffff, rs0, 2);
        rs1 += __shfl_xor_sync(0xffffffff, rs1, 1);
        rs1 += __shfl_xor_sync(0xffffffff, rs1, 2);
        lsum0 += rs0; lsum1 += rs1;

        // ---- O += P V (3-term fp16) ----
        #pragma unroll
        for (int kk = 0; kk < 4; kk++) {
            unsigned pp[4], pl[4];
            const int j0 = kk*2, j1 = kk*2 + 1;
            split_pack_h(S[j0][0], S[j0][1], pp[0], pl[0]);
            split_pack_h(S[j0][2], S[j0][3], pp[1], pl[1]);
            split_pack_h(S[j1][0], S[j1][1], pp[2], pl[2]);
            split_pack_h(S[j1][2], S[j1][3], pp[3], pl[3]);
            const unsigned vrow = (kk*16 + vrow_f) * (KST*2);
            #pragma unroll
            for (int jp = 0; jp < 4; jp++) {
                const unsigned voff = vrow + jp*32 + vcol_b;
                unsigned vh0,vh1,vh2,vh3, vl0,vl1,vl2,vl3;
                ldsm_x4_t(vh0, vh1, vh2, vh3, sVh + voff);
                ldsm_x4_t(vl0, vl1, vl2, vl3, sVl + voff);
                mma16816(Oa[2*jp],   pp, vh0, vh1);
                mma16816(Oa[2*jp],   pp, vl0, vl1);
                mma16816(Oa[2*jp],   pl, vh0, vh1);
                mma16816(Oa[2*jp+1], pp, vh2, vh3);
                mma16816(Oa[2*jp+1], pp, vl2, vl3);
                mma16816(Oa[2*jp+1], pl, vh2, vh3);
            }
        }
        __syncthreads();
    }

    const float inv0 = 1.f / lsum0, inv1 = 1.f / lsum1;
    float* Op = Out + ((size_t)b * SEQ + m0) * DMODEL + h * HD;
    #pragma unroll
    for (int jd = 0; jd < 8; jd++) {
        const int c = jd*8 + qc*2;
        float2 v0; v0.x = Oa[jd][0] * inv0; v0.y = Oa[jd][1] * inv0;
        float2 v1; v1.x = Oa[jd][2] * inv1; v1.y = Oa[jd][3] * inv1;
        *(float2*)&Op[(size_t)gr * DMODEL + c]       = v0;
        *(float2*)&Op[(size_t)(gr + 8) * DMODEL + c] = v1;
    }
}

// ---------------------------------------------------------------------------
extern "C" void kernel_launch(void* const* d_in, const int* in_sizes, int n_in,
                              void* d_out, int out_size)
{
    const float* X    = (const float*)d_in[0];
    const float* Wqkv = (const float*)d_in[1];
    const float* bqkv = (const float*)d_in[2];

    float* out  = (float*)d_out;
    float* Kout = (float*)d_out + ELEMS;
    float* Vout = (float*)d_out + 2 * (size_t)ELEMS;

    static bool attr_done = false;
    if (!attr_done) {
        cudaFuncSetAttribute(qkv_gemm_tc, cudaFuncAttributeMaxDynamicSharedMemorySize, 2 * STG_G);
        cudaFuncSetAttribute(attn_tc,     cudaFuncAttributeMaxDynamicSharedMemorySize, STG_A);
        attr_done = true;
    }

    convert_planes<<<512, 256>>>((const float4*)X, (const float4*)Wqkv);

    dim3 ggrid(N_GEMM / 128, M_GEMM / 128);   // (24, 32)
    qkv_gemm_tc<<<ggrid, 256, 2 * STG_G>>>(bqkv, Kout, Vout);

    dim3 agrid(SEQ / 64, BS * NH);            // (32, 32)
    attn_tc<<<agrid, 128, STG_A>>>(out);
}